// round 6
// baseline (speedup 1.0000x reference)
#include <cuda_runtime.h>
#include <math.h>

#define BB 2
#define CDIM 128
#define QSPAT 4096   // 16^3
#define NS 512       // 8^3

typedef unsigned long long ULL;

// ---- packed f32x2 helpers (sm_100a) ----
__device__ __forceinline__ ULL pk2(float lo, float hi) {
    ULL r; asm("mov.b64 %0,{%1,%2};" : "=l"(r) : "f"(lo), "f"(hi)); return r;
}
__device__ __forceinline__ void upk2(ULL v, float& lo, float& hi) {
    asm("mov.b64 {%0,%1}, %2;" : "=f"(lo), "=f"(hi) : "l"(v));
}
__device__ __forceinline__ ULL fma2(ULL a, ULL b, ULL c) {
    ULL d; asm("fma.rn.f32x2 %0,%1,%2,%3;" : "=l"(d) : "l"(a), "l"(b), "l"(c)); return d;
}
__device__ __forceinline__ ULL add2(ULL a, ULL b) {
    ULL d; asm("add.rn.f32x2 %0,%1,%2;" : "=l"(d) : "l"(a), "l"(b)); return d;
}

// ---- scratch (static device globals; no allocation) ----
__device__ float g_Q [BB*CDIM*QSPAT];
__device__ float g_xs[BB*CDIM*NS];
__device__ float g_K [BB*CDIM*NS];
__device__ float g_V [BB*CDIM*NS];
__device__ float g_O [BB*CDIM*QSPAT];

// =====================================================================
// Projection GEMM: out[b][o][p] = bias[o] + sum_c w[o][c]*x[b][c][p]
// C = O = 128. 256 threads, tile 128 o x 64 p, c-chunks of 32.
// f32x2-packed over channel pairs; x staged transposed.
// =====================================================================
__global__ __launch_bounds__(256) void gemm128(
    const float* __restrict__ x,
    const float* __restrict__ w0, const float* __restrict__ b0, float* __restrict__ o0,
    const float* __restrict__ w1, const float* __restrict__ b1, float* __restrict__ o1,
    int P)
{
    const float* w    = blockIdx.z ? w1 : w0;
    const float* bias = blockIdx.z ? b1 : b0;
    float*       out  = blockIdx.z ? o1 : o0;
    const int b     = blockIdx.y;
    const int pbase = blockIdx.x * 64;

    __shared__ float xs2[64 * 36];      // [p][c], stride 36 (16B-aligned rows)
    __shared__ float ws [128 * 32];     // [o][c]

    const int tid   = threadIdx.x;
    const int wi    = tid >> 5;
    const int lane  = tid & 31;
    const int obase = wi * 16;
    const int p0 = lane * 2, p1 = p0 + 1;

    ULL accA[16], accB[16];
#pragma unroll
    for (int j = 0; j < 16; j++) { accA[j] = 0ull; accB[j] = 0ull; }

    for (int cb = 0; cb < 4; cb++) {
        for (int idx = tid; idx < 32 * 64; idx += 256) {
            int c = idx >> 6, p = idx & 63;
            xs2[p * 36 + c] = x[(b * 128 + cb * 32 + c) * P + pbase + p];
        }
        for (int idx = tid; idx < 128 * 32; idx += 256) {
            int oo = idx >> 5, cc = idx & 31;
            ws[oo * 32 + cc] = w[oo * 128 + cb * 32 + cc];
        }
        __syncthreads();
#pragma unroll
        for (int cq = 0; cq < 8; cq++) {
            ulonglong2 xA = *(const ulonglong2*)&xs2[p0 * 36 + cq * 4];
            ulonglong2 xB = *(const ulonglong2*)&xs2[p1 * 36 + cq * 4];
#pragma unroll
            for (int j = 0; j < 16; j++) {
                ulonglong2 wv = *(const ulonglong2*)&ws[(obase + j) * 32 + cq * 4];
                accA[j] = fma2(wv.x, xA.x, accA[j]);
                accA[j] = fma2(wv.y, xA.y, accA[j]);
                accB[j] = fma2(wv.x, xB.x, accB[j]);
                accB[j] = fma2(wv.y, xB.y, accB[j]);
            }
        }
        __syncthreads();
    }
#pragma unroll
    for (int j = 0; j < 16; j++) {
        float bv = bias[obase + j];
        float lo, hi;
        upk2(accA[j], lo, hi); float r0 = lo + hi + bv;
        upk2(accB[j], lo, hi); float r1 = lo + hi + bv;
        *(float2*)&out[(b * 128 + obase + j) * P + pbase + p0] = make_float2(r0, r1);
    }
}

// =====================================================================
// Offsets pipeline + trilinear gather, fully fused (one warp per sample).
// =====================================================================
__global__ __launch_bounds__(128) void offset_sample(
    const float* __restrict__ kvf,
    const float* __restrict__ wdw, const float* __restrict__ bdw,
    const float* __restrict__ lnw, const float* __restrict__ lnb,
    const float* __restrict__ wproj)
{
    const int gw   = (blockIdx.x * 128 + threadIdx.x) >> 5;  // 0..4095
    const int lane = threadIdx.x & 31;
    const int bg   = gw >> 9;
    const int samp = gw & 511;
    const int b = bg >> 2, g = bg & 3;
    const int od = samp >> 6, oh = (samp >> 3) & 7, ow = samp & 7;
    const int ch = g * 32 + lane;

    const float* qc = g_Q + (b * 128 + ch) * QSPAT;
    const float* wc = wdw + lane * 27;
    float acc = bdw[lane];
    const int z0 = od * 2 - 1, y0 = oh * 2 - 1, x0 = ow * 2 - 1;
#pragma unroll
    for (int kz = 0; kz < 3; kz++) {
        int z = z0 + kz; if ((unsigned)z >= 16u) continue;
#pragma unroll
        for (int ky = 0; ky < 3; ky++) {
            int y = y0 + ky; if ((unsigned)y >= 16u) continue;
#pragma unroll
            for (int kx = 0; kx < 3; kx++) {
                int xq = x0 + kx; if ((unsigned)xq >= 16u) continue;
                acc += wc[kz * 9 + ky * 3 + kx] * qc[(z * 16 + y) * 16 + xq];
            }
        }
    }

    float s1 = acc, s2 = acc * acc;
#pragma unroll
    for (int o = 16; o; o >>= 1) {
        s1 += __shfl_xor_sync(0xffffffffu, s1, o);
        s2 += __shfl_xor_sync(0xffffffffu, s2, o);
    }
    float mu  = s1 * (1.f / 32.f);
    float var = s2 * (1.f / 32.f) - mu * mu;
    float xn  = (acc - mu) * rsqrtf(var + 1e-5f) * lnw[lane] + lnb[lane];
    float ge = 0.5f * xn * (1.f + erff(xn * 0.70710678118654752440f));

    float pr[3];
#pragma unroll
    for (int i = 0; i < 3; i++) {
        float t = wproj[i * 32 + lane] * ge;
#pragma unroll
        for (int o = 16; o; o >>= 1) t += __shfl_xor_sync(0xffffffffu, t, o);
        pr[i] = t;
    }

    float gz = tanhf(pr[0]) * 0.25f + ((od + 0.5f) * 0.25f - 1.f);
    float gy = tanhf(pr[1]) * 0.25f + ((oh + 0.5f) * 0.25f - 1.f);
    float gx = tanhf(pr[2]) * 0.25f + ((ow + 0.5f) * 0.25f - 1.f);

    float ix = (gx + 1.f) * 0.5f * 15.f;
    float iy = (gy + 1.f) * 0.5f * 15.f;
    float iz = (gz + 1.f) * 0.5f * 15.f;
    float zf = floorf(iz), yf = floorf(iy), xf = floorf(ix);
    float tz = iz - zf, ty = iy - yf, tx = ix - xf;
    int zi = (int)zf, yi = (int)yf, xi = (int)xf;

    const float* kvc = kvf + (b * 128 + ch) * QSPAT;
    float val = 0.f;
#pragma unroll
    for (int dz = 0; dz < 2; dz++) {
        int z = zi + dz; float wz = dz ? tz : 1.f - tz;
        if ((unsigned)z >= 16u) continue;
#pragma unroll
        for (int dy = 0; dy < 2; dy++) {
            int y = yi + dy; float wy = dy ? ty : 1.f - ty;
            if ((unsigned)y >= 16u) continue;
#pragma unroll
            for (int dx = 0; dx < 2; dx++) {
                int xq = xi + dx; float wx = dx ? tx : 1.f - tx;
                if ((unsigned)xq >= 16u) continue;
                val += wz * wy * wx * kvc[(z * 16 + y) * 16 + xq];
            }
        }
    }
    g_xs[(b * 128 + ch) * NS + samp] = val;
}

// =====================================================================
// Attention, f32x2-packed over the key dim, 1 query per thread.
// K,V channel-major in smem [16][512]. grid = (16 query-chunks, 16 hb),
// 256 threads, 64KB dynamic smem -> 2 blocks/SM = 4 warps/SMSP.
// No max-subtraction (logits tiny for this problem; exact in fp32).
// =====================================================================
__global__ __launch_bounds__(256) void attn_kernel()
{
    extern __shared__ float sm[];
    float* Ks = sm;          // [16][512] channel-major
    float* Vs = sm + 8192;   // [16][512] channel-major

    const int hb = blockIdx.y;
    const int b = hb >> 3, h = hb & 7;
    const int tid = threadIdx.x;

    const float4* K4 = (const float4*)(g_K + (b * 128 + h * 16) * NS);
    const float4* V4 = (const float4*)(g_V + (b * 128 + h * 16) * NS);
    float4* Ks4 = (float4*)Ks;
    float4* Vs4 = (float4*)Vs;
    for (int i = tid; i < 2048; i += 256) {
        Ks4[i] = K4[i];
        Vs4[i] = V4[i];
    }
    __syncthreads();

    const int m = blockIdx.x * 256 + tid;
    const float* Qb = g_Q + (b * 128 + h * 16) * QSPAT;

    ULL q[16];
#pragma unroll
    for (int c = 0; c < 16; c++) {
        float v = Qb[c * QSPAT + m] * 0.25f;   // fold scale HC^-0.5
        q[c] = pk2(v, v);
    }

    ULL a[16];
#pragma unroll
    for (int c = 0; c < 16; c++) a[c] = 0ull;
    ULL l = 0ull;

    for (int t = 0; t < 128; t++) {          // 4 keys per iteration
        ULL s0 = 0ull, s1 = 0ull;
#pragma unroll
        for (int c = 0; c < 16; c++) {
            ulonglong2 k = *(const ulonglong2*)(Ks + c * 512 + 4 * t);
            s0 = fma2(q[c], k.x, s0);
            s1 = fma2(q[c], k.y, s1);
        }
        float ea, eb;
        upk2(s0, ea, eb); ULL p0 = pk2(__expf(ea), __expf(eb));
        upk2(s1, ea, eb); ULL p1 = pk2(__expf(ea), __expf(eb));
        l = add2(l, add2(p0, p1));
#pragma unroll
        for (int c = 0; c < 16; c++) {
            ulonglong2 v = *(const ulonglong2*)(Vs + c * 512 + 4 * t);
            a[c] = fma2(p0, v.x, a[c]);
            a[c] = fma2(p1, v.y, a[c]);
        }
    }

    float la, lb;
    upk2(l, la, lb);
    float inv = 1.f / (la + lb);

    float* Ob = g_O + (b * 128 + h * 16) * QSPAT;
#pragma unroll
    for (int c = 0; c < 16; c++) {
        float xa, xb;
        upk2(a[c], xa, xb);
        Ob[c * QSPAT + m] = (xa + xb) * inv;
    }
}

// =====================================================================
extern "C" void kernel_launch(void* const* d_in, const int* in_sizes, int n_in,
                              void* d_out, int out_size)
{
    (void)in_sizes; (void)n_in; (void)out_size;
    const float* Qf  = (const float*)d_in[0];
    const float* KVf = (const float*)d_in[1];
    const float* wq  = (const float*)d_in[2];
    const float* bq  = (const float*)d_in[3];
    const float* wdw = (const float*)d_in[4];
    const float* bdw = (const float*)d_in[5];
    const float* lnw = (const float*)d_in[6];
    const float* lnb = (const float*)d_in[7];
    const float* wpr = (const float*)d_in[8];
    const float* wk  = (const float*)d_in[9];
    const float* bk  = (const float*)d_in[10];
    const float* wv  = (const float*)d_in[11];
    const float* bv  = (const float*)d_in[12];
    const float* wo  = (const float*)d_in[13];
    const float* bo  = (const float*)d_in[14];
    float* out = (float*)d_out;

    float *gQ, *gxs, *gK, *gV, *gO;
    cudaGetSymbolAddress((void**)&gQ,  g_Q);
    cudaGetSymbolAddress((void**)&gxs, g_xs);
    cudaGetSymbolAddress((void**)&gK,  g_K);
    cudaGetSymbolAddress((void**)&gV,  g_V);
    cudaGetSymbolAddress((void**)&gO,  g_O);

    cudaFuncSetAttribute(attn_kernel,
                         cudaFuncAttributeMaxDynamicSharedMemorySize, 65536);

    // 1) Q projection
    gemm128<<<dim3(QSPAT / 64, BB, 1), 256>>>(Qf, wq, bq, gQ, wq, bq, gQ, QSPAT);

    // 2) offsets + trilinear gather
    offset_sample<<<1024, 128>>>(KVf, wdw, bdw, lnw, lnb, wpr);

    // 3) K and V projections (one launch)
    gemm128<<<dim3(NS / 64, BB, 2), 256>>>(gxs, wk, bk, gK, wv, bv, gV, NS);

    // 4) attention (1 query/thread, 2 blocks/SM)
    attn_kernel<<<dim3(16, 16), 256, 65536>>>();

    // 5) output projection
    gemm128<<<dim3(QSPAT / 64, BB, 1), 256>>>(gO, wo, bo, out, wo, bo, out, QSPAT);
}

// round 7
// speedup vs baseline: 1.0282x; 1.0282x over previous
#include <cuda_runtime.h>
#include <math.h>

#define BB 2
#define CDIM 128
#define QSPAT 4096   // 16^3
#define NS 512       // 8^3

typedef unsigned long long ULL;

// ---- packed f32x2 helpers (sm_100a) ----
__device__ __forceinline__ ULL pk2(float lo, float hi) {
    ULL r; asm("mov.b64 %0,{%1,%2};" : "=l"(r) : "f"(lo), "f"(hi)); return r;
}
__device__ __forceinline__ void upk2(ULL v, float& lo, float& hi) {
    asm("mov.b64 {%0,%1}, %2;" : "=f"(lo), "=f"(hi) : "l"(v));
}
__device__ __forceinline__ ULL fma2(ULL a, ULL b, ULL c) {
    ULL d; asm("fma.rn.f32x2 %0,%1,%2,%3;" : "=l"(d) : "l"(a), "l"(b), "l"(c)); return d;
}
__device__ __forceinline__ ULL add2(ULL a, ULL b) {
    ULL d; asm("add.rn.f32x2 %0,%1,%2;" : "=l"(d) : "l"(a), "l"(b)); return d;
}

// ---- scratch (static device globals; no allocation) ----
__device__ float g_Q [BB*CDIM*QSPAT];
__device__ float g_xs[BB*CDIM*NS];
__device__ float g_K [BB*CDIM*NS];
__device__ float g_V [BB*CDIM*NS];
__device__ float g_pa[2*BB*CDIM*QSPAT];   // [split][b][c][m] unnormalized sum(exp*v)
__device__ float g_pl[2*BB*8*QSPAT];      // [split][b][h][m] sum(exp)

// =====================================================================
// Projection GEMM: out[b][o][p] = bias[o] + sum_c w[o][c]*x[b][c][p]
// C = O = 128. 256 threads, tile 128 o x 64 p, c-chunks of 32.
// =====================================================================
__global__ __launch_bounds__(256) void gemm128(
    const float* __restrict__ x,
    const float* __restrict__ w0, const float* __restrict__ b0, float* __restrict__ o0,
    const float* __restrict__ w1, const float* __restrict__ b1, float* __restrict__ o1,
    int P)
{
    const float* w    = blockIdx.z ? w1 : w0;
    const float* bias = blockIdx.z ? b1 : b0;
    float*       out  = blockIdx.z ? o1 : o0;
    const int b     = blockIdx.y;
    const int pbase = blockIdx.x * 64;

    __shared__ float xs2[64 * 36];      // [p][c], stride 36 (16B-aligned rows)
    __shared__ float ws [128 * 32];     // [o][c]

    const int tid   = threadIdx.x;
    const int wi    = tid >> 5;
    const int lane  = tid & 31;
    const int obase = wi * 16;
    const int p0 = lane * 2, p1 = p0 + 1;

    ULL accA[16], accB[16];
#pragma unroll
    for (int j = 0; j < 16; j++) { accA[j] = 0ull; accB[j] = 0ull; }

    for (int cb = 0; cb < 4; cb++) {
        for (int idx = tid; idx < 32 * 64; idx += 256) {
            int c = idx >> 6, p = idx & 63;
            xs2[p * 36 + c] = x[(b * 128 + cb * 32 + c) * P + pbase + p];
        }
        for (int idx = tid; idx < 128 * 32; idx += 256) {
            int oo = idx >> 5, cc = idx & 31;
            ws[oo * 32 + cc] = w[oo * 128 + cb * 32 + cc];
        }
        __syncthreads();
#pragma unroll
        for (int cq = 0; cq < 8; cq++) {
            ulonglong2 xA = *(const ulonglong2*)&xs2[p0 * 36 + cq * 4];
            ulonglong2 xB = *(const ulonglong2*)&xs2[p1 * 36 + cq * 4];
#pragma unroll
            for (int j = 0; j < 16; j++) {
                ulonglong2 wv = *(const ulonglong2*)&ws[(obase + j) * 32 + cq * 4];
                accA[j] = fma2(wv.x, xA.x, accA[j]);
                accA[j] = fma2(wv.y, xA.y, accA[j]);
                accB[j] = fma2(wv.x, xB.x, accB[j]);
                accB[j] = fma2(wv.y, xB.y, accB[j]);
            }
        }
        __syncthreads();
    }
#pragma unroll
    for (int j = 0; j < 16; j++) {
        float bv = bias[obase + j];
        float lo, hi;
        upk2(accA[j], lo, hi); float r0 = lo + hi + bv;
        upk2(accB[j], lo, hi); float r1 = lo + hi + bv;
        *(float2*)&out[(b * 128 + obase + j) * P + pbase + p0] = make_float2(r0, r1);
    }
}

// =====================================================================
// O-projection GEMM with fused split-K attention combine:
// x[b][c][p] = (pa0 + pa1) / (pl0 + pl1), computed in the load stage.
// =====================================================================
__global__ __launch_bounds__(256) void gemm_out(
    const float* __restrict__ pa, const float* __restrict__ pl,
    const float* __restrict__ w, const float* __restrict__ bias,
    float* __restrict__ out)
{
    const int b     = blockIdx.y;
    const int pbase = blockIdx.x * 64;

    __shared__ float xs2[64 * 36];
    __shared__ float ws [128 * 32];

    const int tid   = threadIdx.x;
    const int wi    = tid >> 5;
    const int lane  = tid & 31;
    const int obase = wi * 16;
    const int p0 = lane * 2, p1 = p0 + 1;

    ULL accA[16], accB[16];
#pragma unroll
    for (int j = 0; j < 16; j++) { accA[j] = 0ull; accB[j] = 0ull; }

    for (int cb = 0; cb < 4; cb++) {
        for (int idx = tid; idx < 32 * 64; idx += 256) {
            int c = idx >> 6, p = idx & 63;
            int gc = cb * 32 + c;
            int pp = pbase + p;
            int hh = gc >> 4;
            float v0 = pa[((0 + b) * 128 + gc) * QSPAT + pp];
            float v1 = pa[((2 + b) * 128 + gc) * QSPAT + pp];
            float l0 = pl[(b * 8 + hh) * QSPAT + pp];
            float l1 = pl[((2 + b) * 8 + hh) * QSPAT + pp];
            xs2[p * 36 + c] = (v0 + v1) / (l0 + l1);
        }
        for (int idx = tid; idx < 128 * 32; idx += 256) {
            int oo = idx >> 5, cc = idx & 31;
            ws[oo * 32 + cc] = w[oo * 128 + cb * 32 + cc];
        }
        __syncthreads();
#pragma unroll
        for (int cq = 0; cq < 8; cq++) {
            ulonglong2 xA = *(const ulonglong2*)&xs2[p0 * 36 + cq * 4];
            ulonglong2 xB = *(const ulonglong2*)&xs2[p1 * 36 + cq * 4];
#pragma unroll
            for (int j = 0; j < 16; j++) {
                ulonglong2 wv = *(const ulonglong2*)&ws[(obase + j) * 32 + cq * 4];
                accA[j] = fma2(wv.x, xA.x, accA[j]);
                accA[j] = fma2(wv.y, xA.y, accA[j]);
                accB[j] = fma2(wv.x, xB.x, accB[j]);
                accB[j] = fma2(wv.y, xB.y, accB[j]);
            }
        }
        __syncthreads();
    }
#pragma unroll
    for (int j = 0; j < 16; j++) {
        float bv = bias[obase + j];
        float lo, hi;
        upk2(accA[j], lo, hi); float r0 = lo + hi + bv;
        upk2(accB[j], lo, hi); float r1 = lo + hi + bv;
        *(float2*)&out[(b * 128 + obase + j) * QSPAT + pbase + p0] = make_float2(r0, r1);
    }
}

// =====================================================================
// Offsets pipeline + trilinear gather, fully fused (one warp per sample).
// =====================================================================
__global__ __launch_bounds__(128) void offset_sample(
    const float* __restrict__ kvf,
    const float* __restrict__ wdw, const float* __restrict__ bdw,
    const float* __restrict__ lnw, const float* __restrict__ lnb,
    const float* __restrict__ wproj)
{
    const int gw   = (blockIdx.x * 128 + threadIdx.x) >> 5;  // 0..4095
    const int lane = threadIdx.x & 31;
    const int bg   = gw >> 9;
    const int samp = gw & 511;
    const int b = bg >> 2, g = bg & 3;
    const int od = samp >> 6, oh = (samp >> 3) & 7, ow = samp & 7;
    const int ch = g * 32 + lane;

    const float* qc = g_Q + (b * 128 + ch) * QSPAT;
    const float* wc = wdw + lane * 27;
    float acc = bdw[lane];
    const int z0 = od * 2 - 1, y0 = oh * 2 - 1, x0 = ow * 2 - 1;
#pragma unroll
    for (int kz = 0; kz < 3; kz++) {
        int z = z0 + kz; if ((unsigned)z >= 16u) continue;
#pragma unroll
        for (int ky = 0; ky < 3; ky++) {
            int y = y0 + ky; if ((unsigned)y >= 16u) continue;
#pragma unroll
            for (int kx = 0; kx < 3; kx++) {
                int xq = x0 + kx; if ((unsigned)xq >= 16u) continue;
                acc += wc[kz * 9 + ky * 3 + kx] * qc[(z * 16 + y) * 16 + xq];
            }
        }
    }

    float s1 = acc, s2 = acc * acc;
#pragma unroll
    for (int o = 16; o; o >>= 1) {
        s1 += __shfl_xor_sync(0xffffffffu, s1, o);
        s2 += __shfl_xor_sync(0xffffffffu, s2, o);
    }
    float mu  = s1 * (1.f / 32.f);
    float var = s2 * (1.f / 32.f) - mu * mu;
    float xn  = (acc - mu) * rsqrtf(var + 1e-5f) * lnw[lane] + lnb[lane];
    float ge = 0.5f * xn * (1.f + erff(xn * 0.70710678118654752440f));

    float pr[3];
#pragma unroll
    for (int i = 0; i < 3; i++) {
        float t = wproj[i * 32 + lane] * ge;
#pragma unroll
        for (int o = 16; o; o >>= 1) t += __shfl_xor_sync(0xffffffffu, t, o);
        pr[i] = t;
    }

    float gz = tanhf(pr[0]) * 0.25f + ((od + 0.5f) * 0.25f - 1.f);
    float gy = tanhf(pr[1]) * 0.25f + ((oh + 0.5f) * 0.25f - 1.f);
    float gx = tanhf(pr[2]) * 0.25f + ((ow + 0.5f) * 0.25f - 1.f);

    float ix = (gx + 1.f) * 0.5f * 15.f;
    float iy = (gy + 1.f) * 0.5f * 15.f;
    float iz = (gz + 1.f) * 0.5f * 15.f;
    float zf = floorf(iz), yf = floorf(iy), xf = floorf(ix);
    float tz = iz - zf, ty = iy - yf, tx = ix - xf;
    int zi = (int)zf, yi = (int)yf, xi = (int)xf;

    const float* kvc = kvf + (b * 128 + ch) * QSPAT;
    float val = 0.f;
#pragma unroll
    for (int dz = 0; dz < 2; dz++) {
        int z = zi + dz; float wz = dz ? tz : 1.f - tz;
        if ((unsigned)z >= 16u) continue;
#pragma unroll
        for (int dy = 0; dy < 2; dy++) {
            int y = yi + dy; float wy = dy ? ty : 1.f - ty;
            if ((unsigned)y >= 16u) continue;
#pragma unroll
            for (int dx = 0; dx < 2; dx++) {
                int xq = xi + dx; float wx = dx ? tx : 1.f - tx;
                if ((unsigned)xq >= 16u) continue;
                val += wz * wy * wx * kvc[(z * 16 + y) * 16 + xq];
            }
        }
    }
    g_xs[(b * 128 + ch) * NS + samp] = val;
}

// =====================================================================
// Attention with split-K: each block handles 256 of 512 keys.
// 2 queries/thread, f32x2-packed over key dim, K/V halves in 32KB smem.
// grid (8 qchunks, 16 hb, 2 splits) = 256 blocks; __launch_bounds__
// forces <=128 regs -> 2 blocks/SM = 4 warps/SMSP, single wave.
// Writes unnormalized partials (summable: no max-rescale used).
// =====================================================================
__global__ __launch_bounds__(256, 2) void attn_split()
{
    __shared__ float Ks[16 * 256];   // [c][256] channel-major half
    __shared__ float Vs[16 * 256];

    const int hb = blockIdx.y;
    const int sp = blockIdx.z;
    const int b = hb >> 3, h = hb & 7;
    const int tid = threadIdx.x;

    const float4* K4 = (const float4*)(g_K + (b * 128 + h * 16) * NS);
    const float4* V4 = (const float4*)(g_V + (b * 128 + h * 16) * NS);
    float4* Ks4 = (float4*)Ks;
    float4* Vs4 = (float4*)Vs;
    for (int i = tid; i < 1024; i += 256) {       // 16 rows x 64 float4
        int c = i >> 6, j = i & 63;
        Ks4[i] = K4[c * 128 + sp * 64 + j];
        Vs4[i] = V4[c * 128 + sp * 64 + j];
    }
    __syncthreads();

    const int m0 = blockIdx.x * 512 + tid;
    const int m1 = m0 + 256;
    const float* Qb = g_Q + (b * 128 + h * 16) * QSPAT;

    ULL q0[16], q1[16];
#pragma unroll
    for (int c = 0; c < 16; c++) {
        float v0 = Qb[c * QSPAT + m0] * 0.25f;  // fold scale HC^-0.5
        float v1 = Qb[c * QSPAT + m1] * 0.25f;
        q0[c] = pk2(v0, v0);
        q1[c] = pk2(v1, v1);
    }

    ULL a0[16], a1[16];
#pragma unroll
    for (int c = 0; c < 16; c++) { a0[c] = 0ull; a1[c] = 0ull; }
    ULL l0 = 0ull, l1 = 0ull;

    for (int t = 0; t < 64; t++) {               // 4 keys per iteration
        ULL s00 = 0ull, s01 = 0ull, s10 = 0ull, s11 = 0ull;
#pragma unroll
        for (int c = 0; c < 16; c++) {
            ulonglong2 k = *(const ulonglong2*)(Ks + c * 256 + 4 * t);
            s00 = fma2(q0[c], k.x, s00);
            s01 = fma2(q0[c], k.y, s01);
            s10 = fma2(q1[c], k.x, s10);
            s11 = fma2(q1[c], k.y, s11);
        }
        float ea, eb;
        upk2(s00, ea, eb); ULL p00 = pk2(__expf(ea), __expf(eb));
        upk2(s01, ea, eb); ULL p01 = pk2(__expf(ea), __expf(eb));
        upk2(s10, ea, eb); ULL p10 = pk2(__expf(ea), __expf(eb));
        upk2(s11, ea, eb); ULL p11 = pk2(__expf(ea), __expf(eb));
        l0 = add2(l0, add2(p00, p01));
        l1 = add2(l1, add2(p10, p11));
#pragma unroll
        for (int c = 0; c < 16; c++) {
            ulonglong2 v = *(const ulonglong2*)(Vs + c * 256 + 4 * t);
            a0[c] = fma2(p00, v.x, a0[c]);
            a0[c] = fma2(p01, v.y, a0[c]);
            a1[c] = fma2(p10, v.x, a1[c]);
            a1[c] = fma2(p11, v.y, a1[c]);
        }
    }

    float la, lb;
    float* Pa = g_pa + ((sp * BB + b) * 128 + h * 16) * QSPAT;
    float* Pl = g_pl + ((sp * BB + b) * 8 + h) * QSPAT;
#pragma unroll
    for (int c = 0; c < 16; c++) {
        float xa, xb;
        upk2(a0[c], xa, xb); Pa[c * QSPAT + m0] = xa + xb;
        upk2(a1[c], xa, xb); Pa[c * QSPAT + m1] = xa + xb;
    }
    upk2(l0, la, lb); Pl[m0] = la + lb;
    upk2(l1, la, lb); Pl[m1] = la + lb;
}

// =====================================================================
extern "C" void kernel_launch(void* const* d_in, const int* in_sizes, int n_in,
                              void* d_out, int out_size)
{
    (void)in_sizes; (void)n_in; (void)out_size;
    const float* Qf  = (const float*)d_in[0];
    const float* KVf = (const float*)d_in[1];
    const float* wq  = (const float*)d_in[2];
    const float* bq  = (const float*)d_in[3];
    const float* wdw = (const float*)d_in[4];
    const float* bdw = (const float*)d_in[5];
    const float* lnw = (const float*)d_in[6];
    const float* lnb = (const float*)d_in[7];
    const float* wpr = (const float*)d_in[8];
    const float* wk  = (const float*)d_in[9];
    const float* bk  = (const float*)d_in[10];
    const float* wv  = (const float*)d_in[11];
    const float* bv  = (const float*)d_in[12];
    const float* wo  = (const float*)d_in[13];
    const float* bo  = (const float*)d_in[14];
    float* out = (float*)d_out;

    float *gQ, *gxs, *gK, *gV, *gpa, *gpl;
    cudaGetSymbolAddress((void**)&gQ,  g_Q);
    cudaGetSymbolAddress((void**)&gxs, g_xs);
    cudaGetSymbolAddress((void**)&gK,  g_K);
    cudaGetSymbolAddress((void**)&gV,  g_V);
    cudaGetSymbolAddress((void**)&gpa, g_pa);
    cudaGetSymbolAddress((void**)&gpl, g_pl);

    // 1) Q projection
    gemm128<<<dim3(QSPAT / 64, BB, 1), 256>>>(Qf, wq, bq, gQ, wq, bq, gQ, QSPAT);

    // 2) offsets + trilinear gather
    offset_sample<<<1024, 128>>>(KVf, wdw, bdw, lnw, lnb, wpr);

    // 3) K and V projections (one launch)
    gemm128<<<dim3(NS / 64, BB, 2), 256>>>(gxs, wk, bk, gK, wv, bv, gV, NS);

    // 4) attention, split-K over 2 halves (2q/thread, 2 blocks/SM)
    attn_split<<<dim3(8, 16, 2), 256>>>();

    // 5) output projection with fused split combine
    gemm_out<<<dim3(QSPAT / 64, BB, 1), 256>>>(gpa, gpl, wo, bo, out);
}

// round 8
// speedup vs baseline: 1.0303x; 1.0021x over previous
#include <cuda_runtime.h>
#include <math.h>

#define BB 2
#define CDIM 128
#define QSPAT 4096   // 16^3
#define NS 512       // 8^3

typedef unsigned long long ULL;

// ---- packed f32x2 helpers (sm_100a) ----
__device__ __forceinline__ ULL pk2(float lo, float hi) {
    ULL r; asm("mov.b64 %0,{%1,%2};" : "=l"(r) : "f"(lo), "f"(hi)); return r;
}
__device__ __forceinline__ void upk2(ULL v, float& lo, float& hi) {
    asm("mov.b64 {%0,%1}, %2;" : "=f"(lo), "=f"(hi) : "l"(v));
}
__device__ __forceinline__ ULL fma2(ULL a, ULL b, ULL c) {
    ULL d; asm("fma.rn.f32x2 %0,%1,%2,%3;" : "=l"(d) : "l"(a), "l"(b), "l"(c)); return d;
}
__device__ __forceinline__ ULL add2(ULL a, ULL b) {
    ULL d; asm("add.rn.f32x2 %0,%1,%2;" : "=l"(d) : "l"(a), "l"(b)); return d;
}

// ---- scratch (static device globals; no allocation) ----
__device__ float g_Q [BB*CDIM*QSPAT];
__device__ float g_xs[BB*CDIM*NS];
__device__ float g_K [BB*CDIM*NS];
__device__ float g_V [BB*CDIM*NS];
__device__ float g_pa[2*BB*CDIM*QSPAT];   // [split][b][c][m] unnormalized sum(exp*v)
__device__ float g_pl[2*BB*8*QSPAT];      // [split][b][h][m] sum(exp)

// =====================================================================
// Projection GEMM: out[b][o][p] = bias[o] + sum_c w[o][c]*x[b][c][p]
// Tile 128o x 32p, 256 threads, scalar FFMA (rt=1), double-buffered
// staging, conflict-free smem. blockIdx.z selects weight set (K vs V).
// =====================================================================
__global__ __launch_bounds__(256) void gemm128(
    const float* __restrict__ x,
    const float* __restrict__ w0, const float* __restrict__ b0, float* __restrict__ o0,
    const float* __restrict__ w1, const float* __restrict__ b1, float* __restrict__ o1,
    int P)
{
    const float* w    = blockIdx.z ? w1 : w0;
    const float* bias = blockIdx.z ? b1 : b0;
    float*       out  = blockIdx.z ? o1 : o0;
    const int b     = blockIdx.y;
    const int pbase = blockIdx.x * 32;

    __shared__ float xs[2][32 * 32];    // [c][p]
    __shared__ float ws[2][128 * 32];   // [o][c]

    const int tid   = threadIdx.x;
    const int wi    = tid >> 5;
    const int lane  = tid & 31;
    const int obase = wi * 16;
    const int xc    = tid >> 5;         // x staging base c (+8k)
    const int wcq   = tid & 7;          // w staging float4 col

    float4 wreg[4];
    float  xreg[4];

    // prefetch chunk 0
#pragma unroll
    for (int k = 0; k < 4; k++) {
        int oo = (tid >> 3) + 32 * k;
        wreg[k] = *(const float4*)&w[oo * 128 + wcq * 4];
        xreg[k] = x[(b * 128 + xc + 8 * k) * P + pbase + lane];
    }
#pragma unroll
    for (int k = 0; k < 4; k++) {
        int oo = (tid >> 3) + 32 * k;
        *(float4*)&ws[0][oo * 32 + wcq * 4] = wreg[k];
        xs[0][(xc + 8 * k) * 32 + lane] = xreg[k];
    }
    __syncthreads();

    float acc[16];
#pragma unroll
    for (int j = 0; j < 16; j++) acc[j] = 0.f;

    for (int cb = 0; cb < 4; cb++) {
        const int cur = cb & 1;
        if (cb < 3) {
#pragma unroll
            for (int k = 0; k < 4; k++) {
                int oo = (tid >> 3) + 32 * k;
                wreg[k] = *(const float4*)&w[oo * 128 + (cb + 1) * 32 + wcq * 4];
                xreg[k] = x[(b * 128 + (cb + 1) * 32 + xc + 8 * k) * P + pbase + lane];
            }
        }
#pragma unroll
        for (int cq = 0; cq < 8; cq++) {
            float x0 = xs[cur][(cq * 4 + 0) * 32 + lane];
            float x1 = xs[cur][(cq * 4 + 1) * 32 + lane];
            float x2 = xs[cur][(cq * 4 + 2) * 32 + lane];
            float x3 = xs[cur][(cq * 4 + 3) * 32 + lane];
#pragma unroll
            for (int j = 0; j < 16; j++) {
                float4 w4 = *(const float4*)&ws[cur][(obase + j) * 32 + cq * 4];
                acc[j] += w4.x * x0;
                acc[j] += w4.y * x1;
                acc[j] += w4.z * x2;
                acc[j] += w4.w * x3;
            }
        }
        if (cb < 3) {
            const int nxt = cur ^ 1;
#pragma unroll
            for (int k = 0; k < 4; k++) {
                int oo = (tid >> 3) + 32 * k;
                *(float4*)&ws[nxt][oo * 32 + wcq * 4] = wreg[k];
                xs[nxt][(xc + 8 * k) * 32 + lane] = xreg[k];
            }
            __syncthreads();
        }
    }
#pragma unroll
    for (int j = 0; j < 16; j++)
        out[(b * 128 + obase + j) * P + pbase + lane] = acc[j] + bias[obase + j];
}

// =====================================================================
// O-projection GEMM with fused split-K combine in the x staging:
// x[c][p] = (pa0 + pa1) / (pl0 + pl1).
// =====================================================================
__global__ __launch_bounds__(256) void gemm_out(
    const float* __restrict__ pa, const float* __restrict__ pl,
    const float* __restrict__ w, const float* __restrict__ bias,
    float* __restrict__ out)
{
    const int b     = blockIdx.y;
    const int pbase = blockIdx.x * 32;

    __shared__ float xs[2][32 * 32];
    __shared__ float ws[2][128 * 32];

    const int tid   = threadIdx.x;
    const int wi    = tid >> 5;
    const int lane  = tid & 31;
    const int obase = wi * 16;
    const int xc    = tid >> 5;
    const int wcq   = tid & 7;
    const int pp    = pbase + lane;

    float4 wreg[4];
    float  xreg[4];

#pragma unroll
    for (int k = 0; k < 4; k++) {
        int oo = (tid >> 3) + 32 * k;
        wreg[k] = *(const float4*)&w[oo * 128 + wcq * 4];
        int gc = xc + 8 * k;
        int hh = gc >> 4;
        float v0 = pa[(b * 128 + gc) * QSPAT + pp];
        float v1 = pa[((2 + b) * 128 + gc) * QSPAT + pp];
        float l0 = pl[(b * 8 + hh) * QSPAT + pp];
        float l1 = pl[((2 + b) * 8 + hh) * QSPAT + pp];
        xreg[k] = (v0 + v1) / (l0 + l1);
    }
#pragma unroll
    for (int k = 0; k < 4; k++) {
        int oo = (tid >> 3) + 32 * k;
        *(float4*)&ws[0][oo * 32 + wcq * 4] = wreg[k];
        xs[0][(xc + 8 * k) * 32 + lane] = xreg[k];
    }
    __syncthreads();

    float acc[16];
#pragma unroll
    for (int j = 0; j < 16; j++) acc[j] = 0.f;

    for (int cb = 0; cb < 4; cb++) {
        const int cur = cb & 1;
        if (cb < 3) {
#pragma unroll
            for (int k = 0; k < 4; k++) {
                int oo = (tid >> 3) + 32 * k;
                wreg[k] = *(const float4*)&w[oo * 128 + (cb + 1) * 32 + wcq * 4];
                int gc = (cb + 1) * 32 + xc + 8 * k;
                int hh = gc >> 4;
                float v0 = pa[(b * 128 + gc) * QSPAT + pp];
                float v1 = pa[((2 + b) * 128 + gc) * QSPAT + pp];
                float l0 = pl[(b * 8 + hh) * QSPAT + pp];
                float l1 = pl[((2 + b) * 8 + hh) * QSPAT + pp];
                xreg[k] = (v0 + v1) / (l0 + l1);
            }
        }
#pragma unroll
        for (int cq = 0; cq < 8; cq++) {
            float x0 = xs[cur][(cq * 4 + 0) * 32 + lane];
            float x1 = xs[cur][(cq * 4 + 1) * 32 + lane];
            float x2 = xs[cur][(cq * 4 + 2) * 32 + lane];
            float x3 = xs[cur][(cq * 4 + 3) * 32 + lane];
#pragma unroll
            for (int j = 0; j < 16; j++) {
                float4 w4 = *(const float4*)&ws[cur][(obase + j) * 32 + cq * 4];
                acc[j] += w4.x * x0;
                acc[j] += w4.y * x1;
                acc[j] += w4.z * x2;
                acc[j] += w4.w * x3;
            }
        }
        if (cb < 3) {
            const int nxt = cur ^ 1;
#pragma unroll
            for (int k = 0; k < 4; k++) {
                int oo = (tid >> 3) + 32 * k;
                *(float4*)&ws[nxt][oo * 32 + wcq * 4] = wreg[k];
                xs[nxt][(xc + 8 * k) * 32 + lane] = xreg[k];
            }
            __syncthreads();
        }
    }
#pragma unroll
    for (int j = 0; j < 16; j++)
        out[(b * 128 + obase + j) * QSPAT + pp] = acc[j] + bias[obase + j];
}

// =====================================================================
// Offsets pipeline + trilinear gather, fully fused (one warp per sample).
// =====================================================================
__global__ __launch_bounds__(128) void offset_sample(
    const float* __restrict__ kvf,
    const float* __restrict__ wdw, const float* __restrict__ bdw,
    const float* __restrict__ lnw, const float* __restrict__ lnb,
    const float* __restrict__ wproj)
{
    const int gw   = (blockIdx.x * 128 + threadIdx.x) >> 5;  // 0..4095
    const int lane = threadIdx.x & 31;
    const int bg   = gw >> 9;
    const int samp = gw & 511;
    const int b = bg >> 2, g = bg & 3;
    const int od = samp >> 6, oh = (samp >> 3) & 7, ow = samp & 7;
    const int ch = g * 32 + lane;

    const float* qc = g_Q + (b * 128 + ch) * QSPAT;
    const float* wc = wdw + lane * 27;
    float acc = bdw[lane];
    const int z0 = od * 2 - 1, y0 = oh * 2 - 1, x0 = ow * 2 - 1;
#pragma unroll
    for (int kz = 0; kz < 3; kz++) {
        int z = z0 + kz; if ((unsigned)z >= 16u) continue;
#pragma unroll
        for (int ky = 0; ky < 3; ky++) {
            int y = y0 + ky; if ((unsigned)y >= 16u) continue;
#pragma unroll
            for (int kx = 0; kx < 3; kx++) {
                int xq = x0 + kx; if ((unsigned)xq >= 16u) continue;
                acc += wc[kz * 9 + ky * 3 + kx] * qc[(z * 16 + y) * 16 + xq];
            }
        }
    }

    float s1 = acc, s2 = acc * acc;
#pragma unroll
    for (int o = 16; o; o >>= 1) {
        s1 += __shfl_xor_sync(0xffffffffu, s1, o);
        s2 += __shfl_xor_sync(0xffffffffu, s2, o);
    }
    float mu  = s1 * (1.f / 32.f);
    float var = s2 * (1.f / 32.f) - mu * mu;
    float xn  = (acc - mu) * rsqrtf(var + 1e-5f) * lnw[lane] + lnb[lane];
    float ge = 0.5f * xn * (1.f + erff(xn * 0.70710678118654752440f));

    float pr[3];
#pragma unroll
    for (int i = 0; i < 3; i++) {
        float t = wproj[i * 32 + lane] * ge;
#pragma unroll
        for (int o = 16; o; o >>= 1) t += __shfl_xor_sync(0xffffffffu, t, o);
        pr[i] = t;
    }

    float gz = tanhf(pr[0]) * 0.25f + ((od + 0.5f) * 0.25f - 1.f);
    float gy = tanhf(pr[1]) * 0.25f + ((oh + 0.5f) * 0.25f - 1.f);
    float gx = tanhf(pr[2]) * 0.25f + ((ow + 0.5f) * 0.25f - 1.f);

    float ix = (gx + 1.f) * 0.5f * 15.f;
    float iy = (gy + 1.f) * 0.5f * 15.f;
    float iz = (gz + 1.f) * 0.5f * 15.f;
    float zf = floorf(iz), yf = floorf(iy), xf = floorf(ix);
    float tz = iz - zf, ty = iy - yf, tx = ix - xf;
    int zi = (int)zf, yi = (int)yf, xi = (int)xf;

    const float* kvc = kvf + (b * 128 + ch) * QSPAT;
    float val = 0.f;
#pragma unroll
    for (int dz = 0; dz < 2; dz++) {
        int z = zi + dz; float wz = dz ? tz : 1.f - tz;
        if ((unsigned)z >= 16u) continue;
#pragma unroll
        for (int dy = 0; dy < 2; dy++) {
            int y = yi + dy; float wy = dy ? ty : 1.f - ty;
            if ((unsigned)y >= 16u) continue;
#pragma unroll
            for (int dx = 0; dx < 2; dx++) {
                int xq = xi + dx; float wx = dx ? tx : 1.f - tx;
                if ((unsigned)xq >= 16u) continue;
                val += wz * wy * wx * kvc[(z * 16 + y) * 16 + xq];
            }
        }
    }
    g_xs[(b * 128 + ch) * NS + samp] = val;
}

// =====================================================================
// Attention, split-K (256 keys/block), QUERY-PAIR packed f32x2:
// q[c] = (q_m0, q_m1); K/V stored duplicated in smem so each LDS.128
// yields 2 keys' dup pairs. Halves q/accum registers vs key-packing
// (~90 regs) -> ptxas scheduling slack at 2 blocks/SM, 4 warps/SMSP.
// Unnormalized partials out (summable; no max-rescale needed).
// =====================================================================
__global__ __launch_bounds__(256, 2) void attn_split()
{
    extern __shared__ float sm[];
    float* Ks = sm;            // [16][256 keys x dup2]
    float* Vs = sm + 16 * 512;

    const int hb = blockIdx.y;
    const int sp = blockIdx.z;
    const int b = hb >> 3, h = hb & 7;
    const int tid = threadIdx.x;

    const float* Kb = g_K + (b * 128 + h * 16) * NS;
    const float* Vb = g_V + (b * 128 + h * 16) * NS;
    for (int i = tid; i < 2048; i += 256) {     // 16 rows x 128 float2
        int c = i >> 7, kk = i & 127;
        float2 kv = *(const float2*)(Kb + c * NS + sp * 256 + kk * 2);
        float2 vv = *(const float2*)(Vb + c * NS + sp * 256 + kk * 2);
        *(float4*)(Ks + c * 512 + kk * 4) = make_float4(kv.x, kv.x, kv.y, kv.y);
        *(float4*)(Vs + c * 512 + kk * 4) = make_float4(vv.x, vv.x, vv.y, vv.y);
    }
    __syncthreads();

    const int m0 = blockIdx.x * 512 + tid;
    const int m1 = m0 + 256;
    const float* Qb = g_Q + (b * 128 + h * 16) * QSPAT;

    ULL q[16];
#pragma unroll
    for (int c = 0; c < 16; c++)
        q[c] = pk2(Qb[c * QSPAT + m0] * 0.25f, Qb[c * QSPAT + m1] * 0.25f);

    ULL a[16];
#pragma unroll
    for (int c = 0; c < 16; c++) a[c] = 0ull;
    ULL l = 0ull;

#pragma unroll 2
    for (int kp = 0; kp < 128; kp++) {          // 2 keys per iteration
        ULL s0 = 0ull, s1 = 0ull;
#pragma unroll
        for (int c = 0; c < 16; c++) {
            ulonglong2 k = *(const ulonglong2*)(Ks + c * 512 + kp * 4);
            s0 = fma2(q[c], k.x, s0);
            s1 = fma2(q[c], k.y, s1);
        }
        float ea, eb;
        upk2(s0, ea, eb); ULL p0 = pk2(__expf(ea), __expf(eb));
        upk2(s1, ea, eb); ULL p1 = pk2(__expf(ea), __expf(eb));
        l = add2(l, add2(p0, p1));
#pragma unroll
        for (int c = 0; c < 16; c++) {
            ulonglong2 v = *(const ulonglong2*)(Vs + c * 512 + kp * 4);
            a[c] = fma2(p0, v.x, a[c]);
            a[c] = fma2(p1, v.y, a[c]);
        }
    }

    float la, lb;
    float* Pa = g_pa + ((sp * BB + b) * 128 + h * 16) * QSPAT;
    float* Pl = g_pl + ((sp * BB + b) * 8 + h) * QSPAT;
#pragma unroll
    for (int c = 0; c < 16; c++) {
        float xa, xb;
        upk2(a[c], xa, xb);
        Pa[c * QSPAT + m0] = xa;
        Pa[c * QSPAT + m1] = xb;
    }
    upk2(l, la, lb);
    Pl[m0] = la;
    Pl[m1] = lb;
}

// =====================================================================
extern "C" void kernel_launch(void* const* d_in, const int* in_sizes, int n_in,
                              void* d_out, int out_size)
{
    (void)in_sizes; (void)n_in; (void)out_size;
    const float* Qf  = (const float*)d_in[0];
    const float* KVf = (const float*)d_in[1];
    const float* wq  = (const float*)d_in[2];
    const float* bq  = (const float*)d_in[3];
    const float* wdw = (const float*)d_in[4];
    const float* bdw = (const float*)d_in[5];
    const float* lnw = (const float*)d_in[6];
    const float* lnb = (const float*)d_in[7];
    const float* wpr = (const float*)d_in[8];
    const float* wk  = (const float*)d_in[9];
    const float* bk  = (const float*)d_in[10];
    const float* wv  = (const float*)d_in[11];
    const float* bv  = (const float*)d_in[12];
    const float* wo  = (const float*)d_in[13];
    const float* bo  = (const float*)d_in[14];
    float* out = (float*)d_out;

    float *gQ, *gxs, *gK, *gV, *gpa, *gpl;
    cudaGetSymbolAddress((void**)&gQ,  g_Q);
    cudaGetSymbolAddress((void**)&gxs, g_xs);
    cudaGetSymbolAddress((void**)&gK,  g_K);
    cudaGetSymbolAddress((void**)&gV,  g_V);
    cudaGetSymbolAddress((void**)&gpa, g_pa);
    cudaGetSymbolAddress((void**)&gpl, g_pl);

    cudaFuncSetAttribute(attn_split,
                         cudaFuncAttributeMaxDynamicSharedMemorySize, 65536);

    // 1) Q projection
    gemm128<<<dim3(QSPAT / 32, BB, 1), 256>>>(Qf, wq, bq, gQ, wq, bq, gQ, QSPAT);

    // 2) offsets + trilinear gather
    offset_sample<<<1024, 128>>>(KVf, wdw, bdw, lnw, lnb, wpr);

    // 3) K and V projections (one launch)
    gemm128<<<dim3(NS / 32, BB, 2), 256>>>(gxs, wk, bk, gK, wv, bv, gV, NS);

    // 4) attention, split-K over 2 halves (query-pair packed)
    attn_split<<<dim3(8, 16, 2), 256, 65536>>>();

    // 5) output projection with fused split combine
    gemm_out<<<dim3(QSPAT / 32, BB, 1), 256>>>(gpa, gpl, wo, bo, out);
}

// round 9
// speedup vs baseline: 1.5569x; 1.5111x over previous
#include <cuda_runtime.h>
#include <math.h>
#include <stdint.h>

#define BB 2
#define CDIM 128
#define QSPAT 4096   // 16^3
#define NS 512       // 8^3

// ---- scratch (static device globals; no allocation) ----
__device__ float g_Q [BB*CDIM*QSPAT];
__device__ float g_xs[BB*CDIM*NS];
__device__ float g_K [BB*CDIM*NS];
__device__ float g_V [BB*CDIM*NS];
__device__ float g_O [BB*CDIM*QSPAT];

// ---- tf32 mma helpers ----
__device__ __forceinline__ uint32_t tf32c(float x) {
    uint32_t r; asm("cvt.rna.tf32.f32 %0, %1;" : "=r"(r) : "f"(x)); return r;
}
__device__ __forceinline__ float ex2a(float x) {
    float r; asm("ex2.approx.f32 %0, %1;" : "=f"(r) : "f"(x)); return r;
}
__device__ __forceinline__ void mma8(float d[4], const uint32_t a[4],
                                     uint32_t b0, uint32_t b1, const float c[4]) {
    asm("mma.sync.aligned.m16n8k8.row.col.f32.tf32.tf32.f32 "
        "{%0,%1,%2,%3},{%4,%5,%6,%7},{%8,%9},{%10,%11,%12,%13};"
        : "=f"(d[0]), "=f"(d[1]), "=f"(d[2]), "=f"(d[3])
        : "r"(a[0]), "r"(a[1]), "r"(a[2]), "r"(a[3]),
          "r"(b0), "r"(b1),
          "f"(c[0]), "f"(c[1]), "f"(c[2]), "f"(c[3]));
}

// =====================================================================
// Projection GEMM: out[b][o][p] = bias[o] + sum_c w[o][c]*x[b][c][p]
// Tile 128o x 32p, 256 threads, scalar FFMA, double-buffered staging.
// =====================================================================
__global__ __launch_bounds__(256) void gemm128(
    const float* __restrict__ x,
    const float* __restrict__ w0, const float* __restrict__ b0, float* __restrict__ o0,
    const float* __restrict__ w1, const float* __restrict__ b1, float* __restrict__ o1,
    int P)
{
    const float* w    = blockIdx.z ? w1 : w0;
    const float* bias = blockIdx.z ? b1 : b0;
    float*       out  = blockIdx.z ? o1 : o0;
    const int b     = blockIdx.y;
    const int pbase = blockIdx.x * 32;

    __shared__ float xs[2][32 * 32];    // [c][p]
    __shared__ float ws[2][128 * 32];   // [o][c]

    const int tid   = threadIdx.x;
    const int wi    = tid >> 5;
    const int lane  = tid & 31;
    const int obase = wi * 16;
    const int xc    = tid >> 5;
    const int wcq   = tid & 7;

    float4 wreg[4];
    float  xreg[4];

#pragma unroll
    for (int k = 0; k < 4; k++) {
        int oo = (tid >> 3) + 32 * k;
        wreg[k] = *(const float4*)&w[oo * 128 + wcq * 4];
        xreg[k] = x[(b * 128 + xc + 8 * k) * P + pbase + lane];
    }
#pragma unroll
    for (int k = 0; k < 4; k++) {
        int oo = (tid >> 3) + 32 * k;
        *(float4*)&ws[0][oo * 32 + wcq * 4] = wreg[k];
        xs[0][(xc + 8 * k) * 32 + lane] = xreg[k];
    }
    __syncthreads();

    float acc[16];
#pragma unroll
    for (int j = 0; j < 16; j++) acc[j] = 0.f;

    for (int cb = 0; cb < 4; cb++) {
        const int cur = cb & 1;
        if (cb < 3) {
#pragma unroll
            for (int k = 0; k < 4; k++) {
                int oo = (tid >> 3) + 32 * k;
                wreg[k] = *(const float4*)&w[oo * 128 + (cb + 1) * 32 + wcq * 4];
                xreg[k] = x[(b * 128 + (cb + 1) * 32 + xc + 8 * k) * P + pbase + lane];
            }
        }
#pragma unroll
        for (int cq = 0; cq < 8; cq++) {
            float x0 = xs[cur][(cq * 4 + 0) * 32 + lane];
            float x1 = xs[cur][(cq * 4 + 1) * 32 + lane];
            float x2 = xs[cur][(cq * 4 + 2) * 32 + lane];
            float x3 = xs[cur][(cq * 4 + 3) * 32 + lane];
#pragma unroll
            for (int j = 0; j < 16; j++) {
                float4 w4 = *(const float4*)&ws[cur][(obase + j) * 32 + cq * 4];
                acc[j] += w4.x * x0;
                acc[j] += w4.y * x1;
                acc[j] += w4.z * x2;
                acc[j] += w4.w * x3;
            }
        }
        if (cb < 3) {
            const int nxt = cur ^ 1;
#pragma unroll
            for (int k = 0; k < 4; k++) {
                int oo = (tid >> 3) + 32 * k;
                *(float4*)&ws[nxt][oo * 32 + wcq * 4] = wreg[k];
                xs[nxt][(xc + 8 * k) * 32 + lane] = xreg[k];
            }
            __syncthreads();
        }
    }
#pragma unroll
    for (int j = 0; j < 16; j++)
        out[(b * 128 + obase + j) * P + pbase + lane] = acc[j] + bias[obase + j];
}

// =====================================================================
// Offsets pipeline + trilinear gather, fully fused (one warp per sample).
// =====================================================================
__global__ __launch_bounds__(128) void offset_sample(
    const float* __restrict__ kvf,
    const float* __restrict__ wdw, const float* __restrict__ bdw,
    const float* __restrict__ lnw, const float* __restrict__ lnb,
    const float* __restrict__ wproj)
{
    const int gw   = (blockIdx.x * 128 + threadIdx.x) >> 5;  // 0..4095
    const int lane = threadIdx.x & 31;
    const int bg   = gw >> 9;
    const int samp = gw & 511;
    const int b = bg >> 2, g = bg & 3;
    const int od = samp >> 6, oh = (samp >> 3) & 7, ow = samp & 7;
    const int ch = g * 32 + lane;

    const float* qc = g_Q + (b * 128 + ch) * QSPAT;
    const float* wc = wdw + lane * 27;
    float acc = bdw[lane];
    const int z0 = od * 2 - 1, y0 = oh * 2 - 1, x0 = ow * 2 - 1;
#pragma unroll
    for (int kz = 0; kz < 3; kz++) {
        int z = z0 + kz; if ((unsigned)z >= 16u) continue;
#pragma unroll
        for (int ky = 0; ky < 3; ky++) {
            int y = y0 + ky; if ((unsigned)y >= 16u) continue;
#pragma unroll
            for (int kx = 0; kx < 3; kx++) {
                int xq = x0 + kx; if ((unsigned)xq >= 16u) continue;
                acc += wc[kz * 9 + ky * 3 + kx] * qc[(z * 16 + y) * 16 + xq];
            }
        }
    }

    float s1 = acc, s2 = acc * acc;
#pragma unroll
    for (int o = 16; o; o >>= 1) {
        s1 += __shfl_xor_sync(0xffffffffu, s1, o);
        s2 += __shfl_xor_sync(0xffffffffu, s2, o);
    }
    float mu  = s1 * (1.f / 32.f);
    float var = s2 * (1.f / 32.f) - mu * mu;
    float xn  = (acc - mu) * rsqrtf(var + 1e-5f) * lnw[lane] + lnb[lane];
    float ge = 0.5f * xn * (1.f + erff(xn * 0.70710678118654752440f));

    float pr[3];
#pragma unroll
    for (int i = 0; i < 3; i++) {
        float t = wproj[i * 32 + lane] * ge;
#pragma unroll
        for (int o = 16; o; o >>= 1) t += __shfl_xor_sync(0xffffffffu, t, o);
        pr[i] = t;
    }

    float gz = tanhf(pr[0]) * 0.25f + ((od + 0.5f) * 0.25f - 1.f);
    float gy = tanhf(pr[1]) * 0.25f + ((oh + 0.5f) * 0.25f - 1.f);
    float gx = tanhf(pr[2]) * 0.25f + ((ow + 0.5f) * 0.25f - 1.f);

    float ix = (gx + 1.f) * 0.5f * 15.f;
    float iy = (gy + 1.f) * 0.5f * 15.f;
    float iz = (gz + 1.f) * 0.5f * 15.f;
    float zf = floorf(iz), yf = floorf(iy), xf = floorf(ix);
    float tz = iz - zf, ty = iy - yf, tx = ix - xf;
    int zi = (int)zf, yi = (int)yf, xi = (int)xf;

    const float* kvc = kvf + (b * 128 + ch) * QSPAT;
    float val = 0.f;
#pragma unroll
    for (int dz = 0; dz < 2; dz++) {
        int z = zi + dz; float wz = dz ? tz : 1.f - tz;
        if ((unsigned)z >= 16u) continue;
#pragma unroll
        for (int dy = 0; dy < 2; dy++) {
            int y = yi + dy; float wy = dy ? ty : 1.f - ty;
            if ((unsigned)y >= 16u) continue;
#pragma unroll
            for (int dx = 0; dx < 2; dx++) {
                int xq = xi + dx; float wx = dx ? tx : 1.f - tx;
                if ((unsigned)xq >= 16u) continue;
                val += wz * wy * wx * kvc[(z * 16 + y) * 16 + xq];
            }
        }
    }
    g_xs[(b * 128 + ch) * NS + samp] = val;
}

// =====================================================================
// Attention via tf32 mma.sync (m16n8k8). Block = (b,h) x 256 queries,
// 8 warps x 32 queries. K/V staged transposed [key][c] in smem with
// strides 20/24 (bank-conflict-free B-fragment loads). No split-K.
// exp via ex2 (0.25*log2e folded into Q). No max-subtraction.
// grid (16 qchunks, 16 hb), 256 thr, 88KB dyn smem -> 2 blocks/SM.
// =====================================================================
#define KSTR 20
#define VSTR 24
__global__ __launch_bounds__(256) void attn_mma()
{
    extern __shared__ float sm[];
    float* Ks = sm;                  // [512][KSTR]
    float* Vs = sm + 512 * KSTR;     // [512][VSTR]

    const int hb = blockIdx.y;
    const int b = hb >> 3, h = hb & 7;
    const int tid  = threadIdx.x;
    const int w    = tid >> 5;
    const int lane = tid & 31;

    const float* Kb = g_K + (b * 128 + h * 16) * NS;
    const float* Vb = g_V + (b * 128 + h * 16) * NS;
    for (int i = tid; i < 16 * 512; i += 256) {
        int c = i >> 9, k = i & 511;
        Ks[k * KSTR + c] = __uint_as_float(tf32c(Kb[c * NS + k]));
        Vs[k * VSTR + c] = __uint_as_float(tf32c(Vb[c * NS + k]));
    }
    __syncthreads();

    const int r = lane >> 2;         // row in fragment
    const int j = lane & 3;          // quad index
    const int mq = blockIdx.x * 256 + w * 32;
    const float* Qg = g_Q + (b * 128 + h * 16) * QSPAT;
    const float SC = 0.25f * 1.44269504088896f;   // scale * log2(e)

    // Q fragments: [mtile][kstep][4]
    uint32_t qa[2][2][4];
#pragma unroll
    for (int mt = 0; mt < 2; mt++)
#pragma unroll
        for (int ks = 0; ks < 2; ks++) {
            const float* q0 = Qg + (ks * 8 + j) * QSPAT + mq + mt * 16;
            qa[mt][ks][0] = tf32c(q0[r] * SC);
            qa[mt][ks][1] = tf32c(q0[r + 8] * SC);
            qa[mt][ks][2] = tf32c(q0[4 * QSPAT + r] * SC);
            qa[mt][ks][3] = tf32c(q0[4 * QSPAT + r + 8] * SC);
        }

    float o[2][2][4];
    float lsum[2][2];
#pragma unroll
    for (int mt = 0; mt < 2; mt++) {
        lsum[mt][0] = 0.f; lsum[mt][1] = 0.f;
#pragma unroll
        for (int nc = 0; nc < 2; nc++)
#pragma unroll
            for (int i = 0; i < 4; i++) o[mt][nc][i] = 0.f;
    }

    const int src  = (lane & ~3) | (j >> 1);
    const int src2 = src + 2;
    const bool odd = (j & 1);

    for (int kb = 0; kb < 512; kb += 8) {
        // K B-fragments (shared by both m-tiles): k=c, n=key
        uint32_t kf0[2], kf1[2];
#pragma unroll
        for (int ks = 0; ks < 2; ks++) {
            kf0[ks] = __float_as_uint(Ks[(kb + r) * KSTR + ks * 8 + j]);
            kf1[ks] = __float_as_uint(Ks[(kb + r) * KSTR + ks * 8 + j + 4]);
        }
        // V B-fragments: k=key, n=c
        uint32_t vf[2][2];
#pragma unroll
        for (int nc = 0; nc < 2; nc++) {
            vf[nc][0] = __float_as_uint(Vs[(kb + j) * VSTR + nc * 8 + r]);
            vf[nc][1] = __float_as_uint(Vs[(kb + j + 4) * VSTR + nc * 8 + r]);
        }
#pragma unroll
        for (int mt = 0; mt < 2; mt++) {
            float s[4] = {0.f, 0.f, 0.f, 0.f};
            mma8(s, qa[mt][0], kf0[0], kf1[0], s);
            mma8(s, qa[mt][1], kf0[1], kf1[1], s);

            float p0 = ex2a(s[0]), p1 = ex2a(s[1]);
            float p2 = ex2a(s[2]), p3 = ex2a(s[3]);
            lsum[mt][0] += p0 + p1;
            lsum[mt][1] += p2 + p3;

            // transpose C-layout (cols 2j,2j+1) -> A-layout (cols j, j+4)
            float x0 = __shfl_sync(0xffffffffu, p0, src);
            float x1 = __shfl_sync(0xffffffffu, p1, src);
            float y0 = __shfl_sync(0xffffffffu, p0, src2);
            float y1 = __shfl_sync(0xffffffffu, p1, src2);
            float z0 = __shfl_sync(0xffffffffu, p2, src);
            float z1 = __shfl_sync(0xffffffffu, p3, src);
            float u0 = __shfl_sync(0xffffffffu, p2, src2);
            float u1 = __shfl_sync(0xffffffffu, p3, src2);

            uint32_t pa[4];
            pa[0] = tf32c(odd ? x1 : x0);   // (m=r,   key=j)
            pa[1] = tf32c(odd ? z1 : z0);   // (m=r+8, key=j)
            pa[2] = tf32c(odd ? y1 : y0);   // (m=r,   key=j+4)
            pa[3] = tf32c(odd ? u1 : u0);   // (m=r+8, key=j+4)

            mma8(o[mt][0], pa, vf[0][0], vf[0][1], o[mt][0]);
            mma8(o[mt][1], pa, vf[1][0], vf[1][1], o[mt][1]);
        }
    }

    // quad-reduce row sums, normalize, store
    float* Ob = g_O + (b * 128 + h * 16) * QSPAT;
#pragma unroll
    for (int mt = 0; mt < 2; mt++) {
#pragma unroll
        for (int i = 0; i < 2; i++) {
            lsum[mt][i] += __shfl_xor_sync(0xffffffffu, lsum[mt][i], 1);
            lsum[mt][i] += __shfl_xor_sync(0xffffffffu, lsum[mt][i], 2);
        }
        float i0 = 1.f / lsum[mt][0];
        float i1 = 1.f / lsum[mt][1];
        int m0 = mq + mt * 16 + r;
#pragma unroll
        for (int nc = 0; nc < 2; nc++) {
            int cc = nc * 8 + 2 * j;
            Ob[cc * QSPAT + m0]           = o[mt][nc][0] * i0;
            Ob[(cc + 1) * QSPAT + m0]     = o[mt][nc][1] * i0;
            Ob[cc * QSPAT + m0 + 8]       = o[mt][nc][2] * i1;
            Ob[(cc + 1) * QSPAT + m0 + 8] = o[mt][nc][3] * i1;
        }
    }
}

// =====================================================================
extern "C" void kernel_launch(void* const* d_in, const int* in_sizes, int n_in,
                              void* d_out, int out_size)
{
    (void)in_sizes; (void)n_in; (void)out_size;
    const float* Qf  = (const float*)d_in[0];
    const float* KVf = (const float*)d_in[1];
    const float* wq  = (const float*)d_in[2];
    const float* bq  = (const float*)d_in[3];
    const float* wdw = (const float*)d_in[4];
    const float* bdw = (const float*)d_in[5];
    const float* lnw = (const float*)d_in[6];
    const float* lnb = (const float*)d_in[7];
    const float* wpr = (const float*)d_in[8];
    const float* wk  = (const float*)d_in[9];
    const float* bk  = (const float*)d_in[10];
    const float* wv  = (const float*)d_in[11];
    const float* bv  = (const float*)d_in[12];
    const float* wo  = (const float*)d_in[13];
    const float* bo  = (const float*)d_in[14];
    float* out = (float*)d_out;

    float *gQ, *gxs, *gK, *gV, *gO;
    cudaGetSymbolAddress((void**)&gQ,  g_Q);
    cudaGetSymbolAddress((void**)&gxs, g_xs);
    cudaGetSymbolAddress((void**)&gK,  g_K);
    cudaGetSymbolAddress((void**)&gV,  g_V);
    cudaGetSymbolAddress((void**)&gO,  g_O);

    const int ATTN_SMEM = (512 * KSTR + 512 * VSTR) * 4;   // 90112 B
    cudaFuncSetAttribute(attn_mma,
                         cudaFuncAttributeMaxDynamicSharedMemorySize, ATTN_SMEM);

    // 1) Q projection
    gemm128<<<dim3(QSPAT / 32, BB, 1), 256>>>(Qf, wq, bq, gQ, wq, bq, gQ, QSPAT);

    // 2) offsets + trilinear gather
    offset_sample<<<1024, 128>>>(KVf, wdw, bdw, lnw, lnb, wpr);

    // 3) K and V projections (one launch)
    gemm128<<<dim3(NS / 32, BB, 2), 256>>>(gxs, wk, bk, gK, wv, bv, gV, NS);

    // 4) attention (tf32 tensor cores)
    attn_mma<<<dim3(16, 16), 256, ATTN_SMEM>>>();

    // 5) output projection
    gemm128<<<dim3(QSPAT / 32, BB, 1), 256>>>(gO, wo, bo, out, wo, bo, out, QSPAT);
}

// round 11
// speedup vs baseline: 1.9991x; 1.2840x over previous
#include <cuda_runtime.h>
#include <cuda_fp16.h>
#include <math.h>
#include <stdint.h>

#define BB 2
#define CDIM 128
#define QSPAT 4096   // 16^3
#define NS 512       // 8^3

// ---- scratch (static device globals; no allocation) ----
__device__ float g_Q [BB*CDIM*QSPAT];
__device__ float g_Qt[BB*QSPAT*CDIM];   // [b][pos][c] for coalesced conv reads
__device__ float g_xs[BB*CDIM*NS];
__device__ float g_K [BB*CDIM*NS];
__device__ float g_V [BB*CDIM*NS];
__device__ float g_O [BB*CDIM*QSPAT];

// ---- helpers ----
__device__ __forceinline__ float ex2a(float x) {
    float r; asm("ex2.approx.f32 %0, %1;" : "=f"(r) : "f"(x)); return r;
}
// pack (lo, hi) -> f16x2
__device__ __forceinline__ uint32_t packh(float lo, float hi) {
    uint32_t r;
    asm("cvt.rn.f16x2.f32 %0, %1, %2;" : "=r"(r) : "f"(hi), "f"(lo));
    return r;
}
__device__ __forceinline__ void mma16(float d[4], const uint32_t a[4],
                                      uint32_t b0, uint32_t b1, const float c[4]) {
    asm("mma.sync.aligned.m16n8k16.row.col.f32.f16.f16.f32 "
        "{%0,%1,%2,%3},{%4,%5,%6,%7},{%8,%9},{%10,%11,%12,%13};"
        : "=f"(d[0]), "=f"(d[1]), "=f"(d[2]), "=f"(d[3])
        : "r"(a[0]), "r"(a[1]), "r"(a[2]), "r"(a[3]),
          "r"(b0), "r"(b1),
          "f"(c[0]), "f"(c[1]), "f"(c[2]), "f"(c[3]));
}

// =====================================================================
// Projection GEMM: out[b][o][p] = bias[o] + sum_c w[o][c]*x[b][c][p]
// Tile 128o x 32p, 256 threads, scalar FFMA, double-buffered staging.
// Optional transposed output ot[b][p][c] (for the Q projection).
// =====================================================================
__global__ __launch_bounds__(256) void gemm128(
    const float* __restrict__ x,
    const float* __restrict__ w0, const float* __restrict__ b0, float* __restrict__ o0,
    const float* __restrict__ w1, const float* __restrict__ b1, float* __restrict__ o1,
    int P, float* __restrict__ ot)
{
    const float* w    = blockIdx.z ? w1 : w0;
    const float* bias = blockIdx.z ? b1 : b0;
    float*       out  = blockIdx.z ? o1 : o0;
    const int b     = blockIdx.y;
    const int pbase = blockIdx.x * 32;

    __shared__ float xs[2][32 * 32];    // [c][p]
    __shared__ float ws[2][128 * 32];   // [o][c]

    const int tid   = threadIdx.x;
    const int wi    = tid >> 5;
    const int lane  = tid & 31;
    const int obase = wi * 16;
    const int xc    = tid >> 5;
    const int wcq   = tid & 7;

    float4 wreg[4];
    float  xreg[4];

#pragma unroll
    for (int k = 0; k < 4; k++) {
        int oo = (tid >> 3) + 32 * k;
        wreg[k] = *(const float4*)&w[oo * 128 + wcq * 4];
        xreg[k] = x[(b * 128 + xc + 8 * k) * P + pbase + lane];
    }
#pragma unroll
    for (int k = 0; k < 4; k++) {
        int oo = (tid >> 3) + 32 * k;
        *(float4*)&ws[0][oo * 32 + wcq * 4] = wreg[k];
        xs[0][(xc + 8 * k) * 32 + lane] = xreg[k];
    }
    __syncthreads();

    float acc[16];
#pragma unroll
    for (int j = 0; j < 16; j++) acc[j] = 0.f;

    for (int cb = 0; cb < 4; cb++) {
        const int cur = cb & 1;
        if (cb < 3) {
#pragma unroll
            for (int k = 0; k < 4; k++) {
                int oo = (tid >> 3) + 32 * k;
                wreg[k] = *(const float4*)&w[oo * 128 + (cb + 1) * 32 + wcq * 4];
                xreg[k] = x[(b * 128 + (cb + 1) * 32 + xc + 8 * k) * P + pbase + lane];
            }
        }
#pragma unroll
        for (int cq = 0; cq < 8; cq++) {
            float x0 = xs[cur][(cq * 4 + 0) * 32 + lane];
            float x1 = xs[cur][(cq * 4 + 1) * 32 + lane];
            float x2 = xs[cur][(cq * 4 + 2) * 32 + lane];
            float x3 = xs[cur][(cq * 4 + 3) * 32 + lane];
#pragma unroll
            for (int j = 0; j < 16; j++) {
                float4 w4 = *(const float4*)&ws[cur][(obase + j) * 32 + cq * 4];
                acc[j] += w4.x * x0;
                acc[j] += w4.y * x1;
                acc[j] += w4.z * x2;
                acc[j] += w4.w * x3;
            }
        }
        if (cb < 3) {
            const int nxt = cur ^ 1;
#pragma unroll
            for (int k = 0; k < 4; k++) {
                int oo = (tid >> 3) + 32 * k;
                *(float4*)&ws[nxt][oo * 32 + wcq * 4] = wreg[k];
                xs[nxt][(xc + 8 * k) * 32 + lane] = xreg[k];
            }
            __syncthreads();
        }
    }
    float r[16];
#pragma unroll
    for (int j = 0; j < 16; j++) {
        r[j] = acc[j] + bias[obase + j];
        out[(b * 128 + obase + j) * P + pbase + lane] = r[j];
    }
    if (ot) {
        float* tp = ot + (b * P + pbase + lane) * 128 + obase;
#pragma unroll
        for (int k = 0; k < 4; k++)
            *(float4*)&tp[k * 4] = make_float4(r[k*4], r[k*4+1], r[k*4+2], r[k*4+3]);
    }
}

// =====================================================================
// Offsets pipeline + trilinear gather, fully fused (one warp per sample).
// Conv reads g_Qt [pos][c] -> coalesced 128B per tap.
// =====================================================================
__global__ __launch_bounds__(128) void offset_sample(
    const float* __restrict__ kvf,
    const float* __restrict__ wdw, const float* __restrict__ bdw,
    const float* __restrict__ lnw, const float* __restrict__ lnb,
    const float* __restrict__ wproj)
{
    const int gw   = (blockIdx.x * 128 + threadIdx.x) >> 5;  // 0..4095
    const int lane = threadIdx.x & 31;
    const int bg   = gw >> 9;
    const int samp = gw & 511;
    const int b = bg >> 2, g = bg & 3;
    const int od = samp >> 6, oh = (samp >> 3) & 7, ow = samp & 7;
    const int ch = g * 32 + lane;

    const float* qt = g_Qt + (long long)b * QSPAT * 128 + g * 32 + lane;
    const float* wc = wdw + lane * 27;
    float acc = bdw[lane];
    const int z0 = od * 2 - 1, y0 = oh * 2 - 1, x0 = ow * 2 - 1;
#pragma unroll
    for (int kz = 0; kz < 3; kz++) {
        int z = z0 + kz; if ((unsigned)z >= 16u) continue;
#pragma unroll
        for (int ky = 0; ky < 3; ky++) {
            int y = y0 + ky; if ((unsigned)y >= 16u) continue;
#pragma unroll
            for (int kx = 0; kx < 3; kx++) {
                int xq = x0 + kx; if ((unsigned)xq >= 16u) continue;
                acc += wc[kz * 9 + ky * 3 + kx] * qt[((z * 16 + y) * 16 + xq) * 128];
            }
        }
    }

    float s1 = acc, s2 = acc * acc;
#pragma unroll
    for (int o = 16; o; o >>= 1) {
        s1 += __shfl_xor_sync(0xffffffffu, s1, o);
        s2 += __shfl_xor_sync(0xffffffffu, s2, o);
    }
    float mu  = s1 * (1.f / 32.f);
    float var = s2 * (1.f / 32.f) - mu * mu;
    float xn  = (acc - mu) * rsqrtf(var + 1e-5f) * lnw[lane] + lnb[lane];
    float ge = 0.5f * xn * (1.f + erff(xn * 0.70710678118654752440f));

    float pr[3];
#pragma unroll
    for (int i = 0; i < 3; i++) {
        float t = wproj[i * 32 + lane] * ge;
#pragma unroll
        for (int o = 16; o; o >>= 1) t += __shfl_xor_sync(0xffffffffu, t, o);
        pr[i] = t;
    }

    float gz = tanhf(pr[0]) * 0.25f + ((od + 0.5f) * 0.25f - 1.f);
    float gy = tanhf(pr[1]) * 0.25f + ((oh + 0.5f) * 0.25f - 1.f);
    float gx = tanhf(pr[2]) * 0.25f + ((ow + 0.5f) * 0.25f - 1.f);

    float ix = (gx + 1.f) * 0.5f * 15.f;
    float iy = (gy + 1.f) * 0.5f * 15.f;
    float iz = (gz + 1.f) * 0.5f * 15.f;
    float zf = floorf(iz), yf = floorf(iy), xf = floorf(ix);
    float tz = iz - zf, ty = iy - yf, tx = ix - xf;
    int zi = (int)zf, yi = (int)yf, xi = (int)xf;

    const float* kvc = kvf + (b * 128 + ch) * QSPAT;
    float val = 0.f;
#pragma unroll
    for (int dz = 0; dz < 2; dz++) {
        int z = zi + dz; float wz = dz ? tz : 1.f - tz;
        if ((unsigned)z >= 16u) continue;
#pragma unroll
        for (int dy = 0; dy < 2; dy++) {
            int y = yi + dy; float wy = dy ? ty : 1.f - ty;
            if ((unsigned)y >= 16u) continue;
#pragma unroll
            for (int dx = 0; dx < 2; dx++) {
                int xq = xi + dx; float wx = dx ? tx : 1.f - tx;
                if ((unsigned)xq >= 16u) continue;
                val += wz * wy * wx * kvc[(z * 16 + y) * 16 + xq];
            }
        }
    }
    g_xs[(b * 128 + ch) * NS + samp] = val;
}

// =====================================================================
// Attention via fp16 mma m16n8k16. The QK C-fragment maps DIRECTLY to
// the AV A-fragment after exp + f16x2 pack: zero shuffles.
// Block = 128 thr (4 warps x 32 queries), grid (32 qchunks, 16 hb).
// Ks [key][c] stride 24 halfs; Vs [c][key] stride 520 halfs (both
// verified bank-conflict-free). 41KB smem -> ~5 blocks/SM.
// exp via ex2 (0.25*log2e folded into Q). No max-subtraction.
// =====================================================================
#define KSTRH 24
#define VSTRH 520
__global__ __launch_bounds__(128) void attn_fp16()
{
    extern __shared__ __half smh[];
    __half* Ks = smh;                  // [512][KSTRH]
    __half* Vs = smh + 512 * KSTRH;    // [16][VSTRH]

    const int hb = blockIdx.y;
    const int b = hb >> 3, h = hb & 7;
    const int tid  = threadIdx.x;
    const int w    = tid >> 5;
    const int lane = tid & 31;

    const float* Kb = g_K + (b * 128 + h * 16) * NS;
    const float* Vb = g_V + (b * 128 + h * 16) * NS;
    for (int i = tid; i < 16 * 512; i += 128) {
        int c = i >> 9, k = i & 511;
        Ks[k * KSTRH + c] = __float2half_rn(Kb[c * NS + k]);
        Vs[c * VSTRH + k] = __float2half_rn(Vb[c * NS + k]);
    }
    __syncthreads();

    const int r = lane >> 2;         // gid
    const int j = lane & 3;          // ctid
    const int mq = blockIdx.x * 128 + w * 32;
    const float* Qg = g_Q + (b * 128 + h * 16) * QSPAT;
    const float SC = 0.25f * 1.44269504088896f;   // scale * log2(e)

    // Q A-fragments (k = c = 16, one k-step): [mtile][4]
    uint32_t qa[2][4];
#pragma unroll
    for (int mt = 0; mt < 2; mt++) {
        int m = mq + mt * 16 + r;
#pragma unroll
        for (int half_k = 0; half_k < 2; half_k++) {   // c 0-7 / 8-15
            int c0 = half_k * 8 + 2 * j;
            float qlo0 = Qg[c0 * QSPAT + m] * SC;
            float qhi0 = Qg[(c0 + 1) * QSPAT + m] * SC;
            float qlo1 = Qg[c0 * QSPAT + m + 8] * SC;
            float qhi1 = Qg[(c0 + 1) * QSPAT + m + 8] * SC;
            qa[mt][half_k * 2]     = packh(qlo0, qhi0);
            qa[mt][half_k * 2 + 1] = packh(qlo1, qhi1);
        }
    }

    float o[2][2][4];
    float lsum[2][2];
#pragma unroll
    for (int mt = 0; mt < 2; mt++) {
        lsum[mt][0] = 0.f; lsum[mt][1] = 0.f;
#pragma unroll
        for (int nc = 0; nc < 2; nc++)
#pragma unroll
            for (int i = 0; i < 4; i++) o[mt][nc][i] = 0.f;
    }

    for (int kb = 0; kb < 512; kb += 16) {
        // K B-fragments: B[k=c][n=key], n-tiles nt over keys kb+8nt+r
        uint32_t kf[2][2];
#pragma unroll
        for (int nt = 0; nt < 2; nt++) {
            const __half* kr = Ks + (kb + 8 * nt + r) * KSTRH;
            kf[nt][0] = *(const uint32_t*)(kr + 2 * j);
            kf[nt][1] = *(const uint32_t*)(kr + 2 * j + 8);
        }
        // V B-fragments: B[k=key][n=c]
        uint32_t vf[2][2];
#pragma unroll
        for (int nc = 0; nc < 2; nc++) {
            const __half* vr = Vs + (8 * nc + r) * VSTRH + kb;
            vf[nc][0] = *(const uint32_t*)(vr + 2 * j);
            vf[nc][1] = *(const uint32_t*)(vr + 2 * j + 8);
        }
#pragma unroll
        for (int mt = 0; mt < 2; mt++) {
            float s0[4] = {0.f, 0.f, 0.f, 0.f};
            float s1[4] = {0.f, 0.f, 0.f, 0.f};
            mma16(s0, qa[mt], kf[0][0], kf[0][1], s0);   // keys kb..kb+7
            mma16(s1, qa[mt], kf[1][0], kf[1][1], s1);   // keys kb+8..kb+15

            float p00 = ex2a(s0[0]), p01 = ex2a(s0[1]);
            float p02 = ex2a(s0[2]), p03 = ex2a(s0[3]);
            float p10 = ex2a(s1[0]), p11 = ex2a(s1[1]);
            float p12 = ex2a(s1[2]), p13 = ex2a(s1[3]);
            lsum[mt][0] += (p00 + p01) + (p10 + p11);
            lsum[mt][1] += (p02 + p03) + (p12 + p13);

            // P A-fragment = packed C-fragments (no shuffles)
            uint32_t pa[4];
            pa[0] = packh(p00, p01);   // row r,   keys kb+2j,2j+1
            pa[1] = packh(p02, p03);   // row r+8
            pa[2] = packh(p10, p11);   // row r,   keys kb+8+2j
            pa[3] = packh(p12, p13);   // row r+8

            mma16(o[mt][0], pa, vf[0][0], vf[0][1], o[mt][0]);
            mma16(o[mt][1], pa, vf[1][0], vf[1][1], o[mt][1]);
        }
    }

    // quad-reduce row sums, normalize, store
    float* Ob = g_O + (b * 128 + h * 16) * QSPAT;
#pragma unroll
    for (int mt = 0; mt < 2; mt++) {
#pragma unroll
        for (int i = 0; i < 2; i++) {
            lsum[mt][i] += __shfl_xor_sync(0xffffffffu, lsum[mt][i], 1);
            lsum[mt][i] += __shfl_xor_sync(0xffffffffu, lsum[mt][i], 2);
        }
        float i0 = 1.f / lsum[mt][0];
        float i1 = 1.f / lsum[mt][1];
        int m0 = mq + mt * 16 + r;
#pragma unroll
        for (int nc = 0; nc < 2; nc++) {
            int cc = nc * 8 + 2 * j;
            Ob[cc * QSPAT + m0]           = o[mt][nc][0] * i0;
            Ob[(cc + 1) * QSPAT + m0]     = o[mt][nc][1] * i0;
            Ob[cc * QSPAT + m0 + 8]       = o[mt][nc][2] * i1;
            Ob[(cc + 1) * QSPAT + m0 + 8] = o[mt][nc][3] * i1;
        }
    }
}

// =====================================================================
extern "C" void kernel_launch(void* const* d_in, const int* in_sizes, int n_in,
                              void* d_out, int out_size)
{
    (void)in_sizes; (void)n_in; (void)out_size;
    const float* Qf  = (const float*)d_in[0];
    const float* KVf = (const float*)d_in[1];
    const float* wq  = (const float*)d_in[2];
    const float* bq  = (const float*)d_in[3];
    const float* wdw = (const float*)d_in[4];
    const float* bdw = (const float*)d_in[5];
    const float* lnw = (const float*)d_in[6];
    const float* lnb = (const float*)d_in[7];
    const float* wpr = (const float*)d_in[8];
    const float* wk  = (const float*)d_in[9];
    const float* bk  = (const float*)d_in[10];
    const float* wv  = (const float*)d_in[11];
    const float* bv  = (const float*)d_in[12];
    const float* wo  = (const float*)d_in[13];
    const float* bo  = (const float*)d_in[14];
    float* out = (float*)d_out;

    float *gQ, *gQt, *gxs, *gK, *gV, *gO;
    cudaGetSymbolAddress((void**)&gQ,  g_Q);
    cudaGetSymbolAddress((void**)&gQt, g_Qt);
    cudaGetSymbolAddress((void**)&gxs, g_xs);
    cudaGetSymbolAddress((void**)&gK,  g_K);
    cudaGetSymbolAddress((void**)&gV,  g_V);
    cudaGetSymbolAddress((void**)&gO,  g_O);

    const int ATTN_SMEM = (512 * KSTRH + 16 * VSTRH) * 2;   // 41216 B
    cudaFuncSetAttribute(attn_fp16,
                         cudaFuncAttributeMaxDynamicSharedMemorySize, ATTN_SMEM);

    // 1) Q projection (+ transposed copy for the conv)
    gemm128<<<dim3(QSPAT / 32, BB, 1), 256>>>(Qf, wq, bq, gQ, wq, bq, gQ, QSPAT, gQt);

    // 2) offsets + trilinear gather
    offset_sample<<<1024, 128>>>(KVf, wdw, bdw, lnw, lnb, wpr);

    // 3) K and V projections (one launch)
    gemm128<<<dim3(NS / 32, BB, 2), 256>>>(gxs, wk, bk, gK, wv, bv, gV, NS, nullptr);

    // 4) attention (fp16 tensor cores, shuffle-free softmax pipeline)
    attn_fp16<<<dim3(32, 16), 128, ATTN_SMEM>>>();

    // 5) output projection
    gemm128<<<dim3(QSPAT / 32, BB, 1), 256>>>(gO, wo, bo, out, wo, bo, out, QSPAT, nullptr);
}

// round 13
// speedup vs baseline: 3.0462x; 1.5238x over previous
#include <cuda_runtime.h>
#include <cuda_fp16.h>
#include <math.h>
#include <stdint.h>

#define BB 2
#define CDIM 128
#define QSPAT 4096   // 16^3
#define NS 512       // 8^3

// ---- scratch (static device globals; no allocation) ----
__device__ __half g_Qh[BB*QSPAT*CDIM];   // [b][pos][c] fp16 (conv + attn A-frags)
__device__ float  g_xs[BB*CDIM*NS];
__device__ __half g_Kh[BB*NS*CDIM];      // [b][key][c] fp16, pre-scaled by 0.25*log2e
__device__ __half g_Vh[BB*CDIM*NS];      // [b][c][key] fp16
__device__ float  g_O [BB*CDIM*QSPAT];

// ---- helpers ----
__device__ __forceinline__ float ex2a(float x) {
    float r; asm("ex2.approx.f32 %0, %1;" : "=f"(r) : "f"(x)); return r;
}
__device__ __forceinline__ uint32_t packh(float lo, float hi) {
    uint32_t r;
    asm("cvt.rn.f16x2.f32 %0, %1, %2;" : "=r"(r) : "f"(hi), "f"(lo));
    return r;
}
__device__ __forceinline__ void mma16(float d[4], const uint32_t a[4],
                                      uint32_t b0, uint32_t b1, const float c[4]) {
    asm("mma.sync.aligned.m16n8k16.row.col.f32.f16.f16.f32 "
        "{%0,%1,%2,%3},{%4,%5,%6,%7},{%8,%9},{%10,%11,%12,%13};"
        : "=f"(d[0]), "=f"(d[1]), "=f"(d[2]), "=f"(d[3])
        : "r"(a[0]), "r"(a[1]), "r"(a[2]), "r"(a[3]),
          "r"(b0), "r"(b1),
          "f"(c[0]), "f"(c[1]), "f"(c[2]), "f"(c[3]));
}

// =====================================================================
// fp16-mma projection GEMM: out[o][p] = bias[o] + sum_c w[o][c]*x[c][p]
// o = c = 128; p-tile 64 per block; 128 threads (4 warps, each 32 o).
// Full K staged once (one sync). Epilogue modes:
//   0: fp32 natural [o][P]         (O projection / final output)
//   1: fp16 natural pairs [o][P]   (V)
//   2: fp16 transposed [p][128c]   (Q, K; scale osc folded in)
// =====================================================================
#define GHS 68            // smem row stride in uint32 words (136 halfs)
#define GH_SMEM ((128 + 64) * GHS * 4)

__global__ __launch_bounds__(128) void gemm_h(
    const float* __restrict__ x, int P,
    const float* __restrict__ w0, const float* __restrict__ b0, void* out0, int mode0, float sc0,
    const float* __restrict__ w1, const float* __restrict__ b1, void* out1, int mode1, float sc1)
{
    const float* w    = blockIdx.z ? w1 : w0;
    const float* bias = blockIdx.z ? b1 : b0;
    void*        outp = blockIdx.z ? out1 : out0;
    const int    mode = blockIdx.z ? mode1 : mode0;
    const float  osc  = blockIdx.z ? sc1 : sc0;

    const int b     = blockIdx.y;
    const int pbase = blockIdx.x * 64;

    extern __shared__ uint32_t smu[];
    uint32_t* whu = smu;               // [128 o][GHS]
    uint32_t* xhu = smu + 128 * GHS;   // [64 p][GHS]

    const int tid  = threadIdx.x;
    const int wi   = tid >> 5;
    const int lane = tid & 31;
    const int r    = lane >> 2;
    const int j    = lane & 3;

    // stage w rows [32wi, 32wi+32) as fp16 pairs
    for (int i = 0; i < 32; i++) {
        int o = wi * 32 + i;
        float2 v0 = *(const float2*)&w[o * 128 + 2 * lane];
        float2 v1 = *(const float2*)&w[o * 128 + 64 + 2 * lane];
        whu[o * GHS + lane]      = packh(v0.x, v0.y);
        whu[o * GHS + 32 + lane] = packh(v1.x, v1.y);
    }
    // stage x transposed [p][c] as fp16 c-pairs
    for (int i = 0; i < 16; i++) {
        int c = 2 * (wi + 4 * i);
        const float* x0 = x + ((size_t)b * 128 + c) * P + pbase;
        const float* x1 = x0 + P;
#pragma unroll
        for (int hf = 0; hf < 2; hf++) {
            int p = hf * 32 + lane;
            xhu[p * GHS + (c >> 1)] = packh(x0[p], x1[p]);
        }
    }
    __syncthreads();

    float acc[2][8][4];
#pragma unroll
    for (int mt = 0; mt < 2; mt++)
#pragma unroll
        for (int nt = 0; nt < 8; nt++)
#pragma unroll
            for (int i = 0; i < 4; i++) acc[mt][nt][i] = 0.f;

    const int ob = wi * 32;
#pragma unroll
    for (int ks = 0; ks < 8; ks++) {
        uint32_t af[2][4];
#pragma unroll
        for (int mt = 0; mt < 2; mt++) {
            int o = ob + mt * 16;
            af[mt][0] = whu[(o + r) * GHS + ks * 8 + j];
            af[mt][1] = whu[(o + r + 8) * GHS + ks * 8 + j];
            af[mt][2] = whu[(o + r) * GHS + ks * 8 + 4 + j];
            af[mt][3] = whu[(o + r + 8) * GHS + ks * 8 + 4 + j];
        }
#pragma unroll
        for (int nt = 0; nt < 8; nt++) {
            uint32_t bf0 = xhu[(nt * 8 + r) * GHS + ks * 8 + j];
            uint32_t bf1 = xhu[(nt * 8 + r) * GHS + ks * 8 + 4 + j];
            mma16(acc[0][nt], af[0], bf0, bf1, acc[0][nt]);
            mma16(acc[1][nt], af[1], bf0, bf1, acc[1][nt]);
        }
    }

    if (mode == 0) {                       // fp32 natural
        float* out = (float*)outp;
#pragma unroll
        for (int mt = 0; mt < 2; mt++) {
            int o0 = ob + mt * 16 + r;
            float bv0 = bias[o0], bv1 = bias[o0 + 8];
#pragma unroll
            for (int nt = 0; nt < 8; nt++) {
                int p = pbase + nt * 8 + 2 * j;
                *(float2*)&out[((size_t)b * 128 + o0) * P + p] =
                    make_float2(acc[mt][nt][0] + bv0, acc[mt][nt][1] + bv0);
                *(float2*)&out[((size_t)b * 128 + o0 + 8) * P + p] =
                    make_float2(acc[mt][nt][2] + bv1, acc[mt][nt][3] + bv1);
            }
        }
    } else if (mode == 1) {                // fp16 natural pairs
        uint32_t* out = (uint32_t*)outp;
        const int Pw = P >> 1;
#pragma unroll
        for (int mt = 0; mt < 2; mt++) {
            int o0 = ob + mt * 16 + r;
            float bv0 = bias[o0], bv1 = bias[o0 + 8];
#pragma unroll
            for (int nt = 0; nt < 8; nt++) {
                int pw = (pbase >> 1) + nt * 4 + j;
                out[((size_t)b * 128 + o0) * Pw + pw] =
                    packh((acc[mt][nt][0] + bv0) * osc, (acc[mt][nt][1] + bv0) * osc);
                out[((size_t)b * 128 + o0 + 8) * Pw + pw] =
                    packh((acc[mt][nt][2] + bv1) * osc, (acc[mt][nt][3] + bv1) * osc);
            }
        }
    } else {                               // fp16 transposed [p][128]
        __syncthreads();
        __half* tr = (__half*)smu;         // [64][136] halfs (272B rows, 16B-aligned)
#pragma unroll
        for (int mt = 0; mt < 2; mt++) {
            int o0 = ob + mt * 16 + r;
            float bv0 = bias[o0], bv1 = bias[o0 + 8];
#pragma unroll
            for (int nt = 0; nt < 8; nt++) {
                int p0 = nt * 8 + 2 * j;
                tr[p0 * 136 + o0]           = __float2half_rn((acc[mt][nt][0] + bv0) * osc);
                tr[(p0 + 1) * 136 + o0]     = __float2half_rn((acc[mt][nt][1] + bv0) * osc);
                tr[p0 * 136 + o0 + 8]       = __float2half_rn((acc[mt][nt][2] + bv1) * osc);
                tr[(p0 + 1) * 136 + o0 + 8] = __float2half_rn((acc[mt][nt][3] + bv1) * osc);
            }
        }
        __syncthreads();
        __half* out = (__half*)outp;
        // 64 rows x 16 uint4 chunks (8 halfs each) = full 128 channels/row
        for (int i = tid; i < 64 * 16; i += 128) {
            int p = i >> 4, seg = i & 15;
            uint4 v = *(const uint4*)&tr[p * 136 + seg * 8];
            *(uint4*)&out[((size_t)b * P + pbase + p) * 128 + seg * 8] = v;
        }
    }
}

// =====================================================================
// Offsets pipeline + trilinear gather (one warp per sample).
// Conv reads g_Qh fp16 [pos][c] -> coalesced 64B per tap.
// =====================================================================
__global__ __launch_bounds__(128) void offset_sample(
    const float* __restrict__ kvf,
    const float* __restrict__ wdw, const float* __restrict__ bdw,
    const float* __restrict__ lnw, const float* __restrict__ lnb,
    const float* __restrict__ wproj)
{
    const int gw   = (blockIdx.x * 128 + threadIdx.x) >> 5;  // 0..4095
    const int lane = threadIdx.x & 31;
    const int bg   = gw >> 9;
    const int samp = gw & 511;
    const int b = bg >> 2, g = bg & 3;
    const int od = samp >> 6, oh = (samp >> 3) & 7, ow = samp & 7;
    const int ch = g * 32 + lane;

    const __half* qt = g_Qh + (size_t)b * QSPAT * 128 + g * 32 + lane;
    const float* wc = wdw + lane * 27;
    float acc = bdw[lane];
    const int z0 = od * 2 - 1, y0 = oh * 2 - 1, x0 = ow * 2 - 1;
#pragma unroll
    for (int kz = 0; kz < 3; kz++) {
        int z = z0 + kz; if ((unsigned)z >= 16u) continue;
#pragma unroll
        for (int ky = 0; ky < 3; ky++) {
            int y = y0 + ky; if ((unsigned)y >= 16u) continue;
#pragma unroll
            for (int kx = 0; kx < 3; kx++) {
                int xq = x0 + kx; if ((unsigned)xq >= 16u) continue;
                acc += wc[kz * 9 + ky * 3 + kx] *
                       __half2float(qt[((z * 16 + y) * 16 + xq) * 128]);
            }
        }
    }

    float s1 = acc, s2 = acc * acc;
#pragma unroll
    for (int o = 16; o; o >>= 1) {
        s1 += __shfl_xor_sync(0xffffffffu, s1, o);
        s2 += __shfl_xor_sync(0xffffffffu, s2, o);
    }
    float mu  = s1 * (1.f / 32.f);
    float var = s2 * (1.f / 32.f) - mu * mu;
    float xn  = (acc - mu) * rsqrtf(var + 1e-5f) * lnw[lane] + lnb[lane];
    float ge = 0.5f * xn * (1.f + erff(xn * 0.70710678118654752440f));

    float pr[3];
#pragma unroll
    for (int i = 0; i < 3; i++) {
        float t = wproj[i * 32 + lane] * ge;
#pragma unroll
        for (int o = 16; o; o >>= 1) t += __shfl_xor_sync(0xffffffffu, t, o);
        pr[i] = t;
    }

    float gz = tanhf(pr[0]) * 0.25f + ((od + 0.5f) * 0.25f - 1.f);
    float gy = tanhf(pr[1]) * 0.25f + ((oh + 0.5f) * 0.25f - 1.f);
    float gx = tanhf(pr[2]) * 0.25f + ((ow + 0.5f) * 0.25f - 1.f);

    float ix = (gx + 1.f) * 0.5f * 15.f;
    float iy = (gy + 1.f) * 0.5f * 15.f;
    float iz = (gz + 1.f) * 0.5f * 15.f;
    float zf = floorf(iz), yf = floorf(iy), xf = floorf(ix);
    float tz = iz - zf, ty = iy - yf, tx = ix - xf;
    int zi = (int)zf, yi = (int)yf, xi = (int)xf;

    const float* kvc = kvf + (b * 128 + ch) * QSPAT;
    float val = 0.f;
#pragma unroll
    for (int dz = 0; dz < 2; dz++) {
        int z = zi + dz; float wz = dz ? tz : 1.f - tz;
        if ((unsigned)z >= 16u) continue;
#pragma unroll
        for (int dy = 0; dy < 2; dy++) {
            int y = yi + dy; float wy = dy ? ty : 1.f - ty;
            if ((unsigned)y >= 16u) continue;
#pragma unroll
            for (int dx = 0; dx < 2; dx++) {
                int xq = xi + dx; float wx = dx ? tx : 1.f - tx;
                if ((unsigned)xq >= 16u) continue;
                val += wz * wy * wx * kvc[(z * 16 + y) * 16 + xq];
            }
        }
    }
    g_xs[(b * 128 + ch) * NS + samp] = val;
}

// =====================================================================
// Attention via fp16 mma m16n8k16 (shuffle-free softmax pipeline).
// Q A-frags loaded straight from g_Qh [pos][c]; K staged by uint4 copy
// from pre-scaled g_Kh [key][c]; V by uint4 row copy from g_Vh [c][key].
// Block 128 thr (4 warps x 32 q), grid (32 qchunks, 16 hb).
// =====================================================================
#define KSTRH 24
#define VSTRH 520
__global__ __launch_bounds__(128) void attn_fp16()
{
    extern __shared__ __half smh[];
    __half* Ks = smh;                  // [512][KSTRH]
    __half* Vs = smh + 512 * KSTRH;    // [16][VSTRH]

    const int hb = blockIdx.y;
    const int b = hb >> 3, h = hb & 7;
    const int tid  = threadIdx.x;
    const int w    = tid >> 5;
    const int lane = tid & 31;

    // stage K (pre-scaled fp16) rows: 32B per key
    const __half* Kb = g_Kh + ((size_t)b * 512) * 128 + h * 16;
    for (int kk = tid; kk < 512; kk += 128) {
        const uint4* s = (const uint4*)(Kb + (size_t)kk * 128);
        uint4 v0 = s[0], v1 = s[1];
        *(uint4*)(Ks + kk * KSTRH) = v0;
        *(uint4*)(Ks + kk * KSTRH + 8) = v1;
    }
    // stage V rows
    const __half* Vb = g_Vh + ((size_t)(b * 128 + h * 16)) * 512;
    for (int i = tid; i < 16 * 64; i += 128) {
        int c = i >> 6, seg = i & 63;
        uint4 v = *(const uint4*)(Vb + (size_t)c * 512 + seg * 8);
        *(uint4*)(Vs + c * VSTRH + seg * 8) = v;
    }
    __syncthreads();

    const int r = lane >> 2;
    const int j = lane & 3;
    const int mq = blockIdx.x * 128 + w * 32;

    // Q A-fragments straight from g_Qh (word index (b*4096+m)*64 + h*8 + j)
    const uint32_t* Qu = (const uint32_t*)g_Qh;
    const size_t qb = ((size_t)b * 4096) * 64 + h * 8 + j;
    uint32_t qa[2][4];
#pragma unroll
    for (int mt = 0; mt < 2; mt++) {
        size_t m = mq + mt * 16;
        qa[mt][0] = Qu[qb + (m + r) * 64];
        qa[mt][1] = Qu[qb + (m + r + 8) * 64];
        qa[mt][2] = Qu[qb + (m + r) * 64 + 4];
        qa[mt][3] = Qu[qb + (m + r + 8) * 64 + 4];
    }

    float o[2][2][4];
    float lsum[2][2];
#pragma unroll
    for (int mt = 0; mt < 2; mt++) {
        lsum[mt][0] = 0.f; lsum[mt][1] = 0.f;
#pragma unroll
        for (int nc = 0; nc < 2; nc++)
#pragma unroll
            for (int i = 0; i < 4; i++) o[mt][nc][i] = 0.f;
    }

    for (int kb = 0; kb < 512; kb += 16) {
        uint32_t kf[2][2];
#pragma unroll
        for (int nt = 0; nt < 2; nt++) {
            const __half* kr = Ks + (kb + 8 * nt + r) * KSTRH;
            kf[nt][0] = *(const uint32_t*)(kr + 2 * j);
            kf[nt][1] = *(const uint32_t*)(kr + 2 * j + 8);
        }
        uint32_t vf[2][2];
#pragma unroll
        for (int nc = 0; nc < 2; nc++) {
            const __half* vr = Vs + (8 * nc + r) * VSTRH + kb;
            vf[nc][0] = *(const uint32_t*)(vr + 2 * j);
            vf[nc][1] = *(const uint32_t*)(vr + 2 * j + 8);
        }
#pragma unroll
        for (int mt = 0; mt < 2; mt++) {
            float s0[4] = {0.f, 0.f, 0.f, 0.f};
            float s1[4] = {0.f, 0.f, 0.f, 0.f};
            mma16(s0, qa[mt], kf[0][0], kf[0][1], s0);
            mma16(s1, qa[mt], kf[1][0], kf[1][1], s1);

            float p00 = ex2a(s0[0]), p01 = ex2a(s0[1]);
            float p02 = ex2a(s0[2]), p03 = ex2a(s0[3]);
            float p10 = ex2a(s1[0]), p11 = ex2a(s1[1]);
            float p12 = ex2a(s1[2]), p13 = ex2a(s1[3]);
            lsum[mt][0] += (p00 + p01) + (p10 + p11);
            lsum[mt][1] += (p02 + p03) + (p12 + p13);

            uint32_t pa[4];
            pa[0] = packh(p00, p01);
            pa[1] = packh(p02, p03);
            pa[2] = packh(p10, p11);
            pa[3] = packh(p12, p13);

            mma16(o[mt][0], pa, vf[0][0], vf[0][1], o[mt][0]);
            mma16(o[mt][1], pa, vf[1][0], vf[1][1], o[mt][1]);
        }
    }

    float* Ob = g_O + (b * 128 + h * 16) * QSPAT;
#pragma unroll
    for (int mt = 0; mt < 2; mt++) {
#pragma unroll
        for (int i = 0; i < 2; i++) {
            lsum[mt][i] += __shfl_xor_sync(0xffffffffu, lsum[mt][i], 1);
            lsum[mt][i] += __shfl_xor_sync(0xffffffffu, lsum[mt][i], 2);
        }
        float i0 = 1.f / lsum[mt][0];
        float i1 = 1.f / lsum[mt][1];
        int m0 = mq + mt * 16 + r;
#pragma unroll
        for (int nc = 0; nc < 2; nc++) {
            int cc = nc * 8 + 2 * j;
            Ob[cc * QSPAT + m0]           = o[mt][nc][0] * i0;
            Ob[(cc + 1) * QSPAT + m0]     = o[mt][nc][1] * i0;
            Ob[cc * QSPAT + m0 + 8]       = o[mt][nc][2] * i1;
            Ob[(cc + 1) * QSPAT + m0 + 8] = o[mt][nc][3] * i1;
        }
    }
}

// =====================================================================
extern "C" void kernel_launch(void* const* d_in, const int* in_sizes, int n_in,
                              void* d_out, int out_size)
{
    (void)in_sizes; (void)n_in; (void)out_size;
    const float* Qf  = (const float*)d_in[0];
    const float* KVf = (const float*)d_in[1];
    const float* wq  = (const float*)d_in[2];
    const float* bq  = (const float*)d_in[3];
    const float* wdw = (const float*)d_in[4];
    const float* bdw = (const float*)d_in[5];
    const float* lnw = (const float*)d_in[6];
    const float* lnb = (const float*)d_in[7];
    const float* wpr = (const float*)d_in[8];
    const float* wk  = (const float*)d_in[9];
    const float* bk  = (const float*)d_in[10];
    const float* wv  = (const float*)d_in[11];
    const float* bv  = (const float*)d_in[12];
    const float* wo  = (const float*)d_in[13];
    const float* bo  = (const float*)d_in[14];
    float* out = (float*)d_out;

    __half *gQh, *gKh, *gVh;
    float *gxs, *gO;
    cudaGetSymbolAddress((void**)&gQh, g_Qh);
    cudaGetSymbolAddress((void**)&gxs, g_xs);
    cudaGetSymbolAddress((void**)&gKh, g_Kh);
    cudaGetSymbolAddress((void**)&gVh, g_Vh);
    cudaGetSymbolAddress((void**)&gO,  g_O);

    const float SC = 0.25f * 1.44269504088896f;   // attn scale * log2(e), folded into K
    const int ATTN_SMEM = (512 * KSTRH + 16 * VSTRH) * 2;   // 41216 B

    cudaFuncSetAttribute(gemm_h,
                         cudaFuncAttributeMaxDynamicSharedMemorySize, GH_SMEM);
    cudaFuncSetAttribute(attn_fp16,
                         cudaFuncAttributeMaxDynamicSharedMemorySize, ATTN_SMEM);

    // 1) Q projection -> fp16 transposed [pos][c]
    gemm_h<<<dim3(QSPAT / 64, BB, 1), 128, GH_SMEM>>>(
        Qf, QSPAT, wq, bq, gQh, 2, 1.0f, wq, bq, gQh, 2, 1.0f);

    // 2) offsets + trilinear gather
    offset_sample<<<1024, 128>>>(KVf, wdw, bdw, lnw, lnb, wpr);

    // 3) K (transposed, pre-scaled) and V (natural) projections
    gemm_h<<<dim3(NS / 64, BB, 2), 128, GH_SMEM>>>(
        gxs, NS, wk, bk, gKh, 2, SC, wv, bv, gVh, 1, 1.0f);

    // 4) attention (fp16 tensor cores)
    attn_fp16<<<dim3(32, 16), 128, ATTN_SMEM>>>();

    // 5) output projection -> fp32 final
    gemm_h<<<dim3(QSPAT / 64, BB, 1), 128, GH_SMEM>>>(
        gO, QSPAT, wo, bo, out, 0, 1.0f, wo, bo, out, 0, 1.0f);
}